// round 8
// baseline (speedup 1.0000x reference)
#include <cuda_runtime.h>
#include <cuda_bf16.h>
#include <cstdint>

#define N_NODES 50000
#define NREL    16
#define NBAS    16
#define DEMB    256
#define DHID    128
#define NEDGE   300000
#define NQUERY  100000
#define EGRID   ((NEDGE + 127) / 128 + 16)

// ---------------- scratch (static __device__ globals; no allocation) ----------------
__device__ int8_t g_Eq1[(size_t)N_NODES * DEMB];
__device__ int8_t g_Eq0[(size_t)N_NODES * DEMB];
__device__ float  g_Es[N_NODES];
__device__ int8_t g_Wq1[(size_t)NREL * DHID * DEMB];
__device__ int8_t g_Wq0[(size_t)NREL * DHID * DEMB];
__device__ float  g_Wsc[NREL * DHID];
__device__ int8_t g_Sq1[DHID * DEMB];
__device__ int8_t g_Sq0[DHID * DEMB];
__device__ float  g_Ssc[DHID];
__device__ int8_t g_xq1[N_NODES * DHID];
__device__ int8_t g_xq0[N_NODES * DHID];
__device__ float  g_xs[N_NODES];
__device__ int8_t g_w1q1[2 * DHID * DHID];
__device__ int8_t g_w1q0[2 * DHID * DHID];
__device__ float  g_w1sc[2 * DHID];
__device__ float g_acc[N_NODES * DHID];
__device__ float g_HPTP[(size_t)N_NODES * 2 * DHID];
__device__ float g_rp[NREL * DHID];
// edge sort
__device__ int g_cnt[NREL];
__device__ int g_off[NREL + 1];
__device__ int g_tilestart[NREL + 1];
__device__ int g_cursor[NREL];
__device__ int g_erow_s[NEDGE];
__device__ int g_ecol_s[NEDGE];

__device__ __forceinline__ uint32_t smem_u32(const void* p) {
    uint32_t a;
    asm("{ .reg .u64 t; cvta.to.shared.u64 t, %1; cvt.u32.u64 %0, t; }" : "=r"(a) : "l"(p));
    return a;
}
__device__ __forceinline__ void ldsm4(uint32_t* r, uint32_t addr) {
    asm volatile("ldmatrix.sync.aligned.m8n8.x4.shared.b16 {%0,%1,%2,%3}, [%4];"
                 : "=r"(r[0]), "=r"(r[1]), "=r"(r[2]), "=r"(r[3]) : "r"(addr));
}
__device__ __forceinline__ void mma_s8(int* d, const uint32_t* a, uint32_t b0, uint32_t b1) {
    asm volatile(
        "mma.sync.aligned.m16n8k32.row.col.s32.s8.s8.s32 "
        "{%0,%1,%2,%3}, {%4,%5,%6,%7}, {%8,%9}, {%0,%1,%2,%3};"
        : "+r"(d[0]), "+r"(d[1]), "+r"(d[2]), "+r"(d[3])
        : "r"(a[0]), "r"(a[1]), "r"(a[2]), "r"(a[3]), "r"(b0), "r"(b1));
}
__device__ __forceinline__ void cp16(uint32_t dst, const void* src, int srcBytes) {
    asm volatile("cp.async.cg.shared.global [%0], [%1], 16, %2;"
                 :: "r"(dst), "l"(src), "r"(srcBytes));
}
#define CP_COMMIT() asm volatile("cp.async.commit_group;" ::: "memory")
template<int Nw> __device__ __forceinline__ void cp_wait() {
    asm volatile("cp.async.wait_group %0;" :: "n"(Nw) : "memory");
}
__device__ __forceinline__ void red_add4(float* p, float a, float b, float c, float d) {
    asm volatile("red.global.add.v4.f32 [%0], {%1,%2,%3,%4};"
                 :: "l"(p), "f"(a), "f"(b), "f"(c), "f"(d) : "memory");
}
__device__ __forceinline__ uint32_t pack4i8(int a, int b, int c, int d) {
    return (uint32_t)(a & 0xff) | ((uint32_t)(b & 0xff) << 8) |
           ((uint32_t)(c & 0xff) << 16) | ((uint32_t)(d & 0xff) << 24);
}
__device__ __forceinline__ void quant1(float v, float inv, int& h, int& l) {
    float q = v * inv;                       // |q| <= 16256
    h = __float2int_rn(q * (1.f / 128.f));
    l = __float2int_rn(q - 128.f * (float)h);
}
__device__ __forceinline__ float recomb(int d1, int d2) {
    return fmaf(128.f, (float)d2, 16384.f * (float)d1);
}

#define TILE8  8192                   // 128 rows x 64 bytes
#define STAGE8 (4 * TILE8)            // 32 KB
#define SMEM8  (2 * STAGE8)           // 64 KB

// smem addressing: 64B rows, 4x16B segs, swizzle seg ^= (row>>1)&3
__device__ __forceinline__ uint32_t sw_off(int row, int seg) {
    return (uint32_t)(row * 64) + ((uint32_t)(seg ^ ((row >> 1) & 3)) << 4);
}
__device__ __forceinline__ uint32_t lds_addr(uint32_t tb, int row0, int ks, int lane) {
    int row = row0 + (lane & 7) + ((lane >> 3) & 1) * 8;
    int seg = ks * 2 + (lane >> 4);
    return tb + sw_off(row, seg);
}

// ============================================================================
// Dense int8 GEMM: C[M,N] = (Aq,As) @ (Bq,Bs)^T ; grid (N/128, ceil(M/128)), 512 thr
// ============================================================================
__global__ __launch_bounds__(512, 1)
void gemm_s8(int M, int K,
             const int8_t* __restrict__ Aq1, const int8_t* __restrict__ Aq0,
             const float* __restrict__ As,
             const int8_t* __restrict__ Bq1, const int8_t* __restrict__ Bq0,
             const float* __restrict__ Bs,
             float* __restrict__ C, int ldc)
{
    extern __shared__ char sm[];
    const uint32_t sbase = smem_u32(sm);
    const int tid  = threadIdx.x;
    const int wid  = tid >> 5;
    const int lane = tid & 31;
    const int wm   = wid & 3;
    const int wn   = wid >> 2;
    const int mBase = blockIdx.y * 128;
    const int nBase = blockIdx.x * 128;

    int d1[2][4][4], d2[2][4][4];
    #pragma unroll
    for (int i = 0; i < 2; ++i)
        #pragma unroll
        for (int j = 0; j < 4; ++j)
            #pragma unroll
            for (int t = 0; t < 4; ++t) { d1[i][j][t] = 0; d2[i][j][t] = 0; }

    const int nk = K >> 6;

    auto issue = [&](int s, int k0) {
        const uint32_t sb = sbase + (uint32_t)s * STAGE8;
        int row = tid >> 2;
        int seg = tid & 3;
        uint32_t so = sw_off(row, seg);
        int gr = mBase + row;
        int okA = (gr < M) ? 16 : 0;
        size_t aoff = (size_t)(okA ? gr : 0) * K + k0 + seg * 16;
        cp16(sb + so,             Aq1 + aoff, okA);
        cp16(sb + TILE8 + so,     Aq0 + aoff, okA);
        size_t boff = (size_t)(nBase + row) * K + k0 + seg * 16;
        cp16(sb + 2 * TILE8 + so, Bq1 + boff, 16);
        cp16(sb + 3 * TILE8 + so, Bq0 + boff, 16);
    };

    issue(0, 0);
    CP_COMMIT();

    for (int c = 0; c < nk; ++c) {
        if (c + 1 < nk) {
            issue((c + 1) & 1, (c + 1) << 6);
            CP_COMMIT();
            cp_wait<1>();
        } else {
            cp_wait<0>();
        }
        __syncthreads();

        const uint32_t bA1 = sbase + (uint32_t)(c & 1) * STAGE8;
        const uint32_t bA0 = bA1 + TILE8;
        const uint32_t bB1 = bA1 + 2 * TILE8;
        const uint32_t bB0 = bA1 + 3 * TILE8;

        #pragma unroll
        for (int ks = 0; ks < 2; ++ks) {
            uint32_t aq1[2][4], aq0[2][4], bq1[2][4], bq0[2][4];
            #pragma unroll
            for (int i = 0; i < 2; ++i) {
                uint32_t ad = lds_addr(0, wm * 32 + i * 16, ks, lane);
                ldsm4(aq1[i], bA1 + ad);
                ldsm4(aq0[i], bA0 + ad);
            }
            #pragma unroll
            for (int j2 = 0; j2 < 2; ++j2) {
                uint32_t bd = lds_addr(0, wn * 32 + j2 * 16, ks, lane);
                ldsm4(bq1[j2], bB1 + bd);
                ldsm4(bq0[j2], bB0 + bd);
            }
            #pragma unroll
            for (int i = 0; i < 2; ++i)
                #pragma unroll
                for (int j2 = 0; j2 < 2; ++j2) {
                    mma_s8(d1[i][j2 * 2],     aq1[i], bq1[j2][0], bq1[j2][2]);
                    mma_s8(d1[i][j2 * 2 + 1], aq1[i], bq1[j2][1], bq1[j2][3]);
                    mma_s8(d2[i][j2 * 2],     aq1[i], bq0[j2][0], bq0[j2][2]);
                    mma_s8(d2[i][j2 * 2 + 1], aq1[i], bq0[j2][1], bq0[j2][3]);
                    mma_s8(d2[i][j2 * 2],     aq0[i], bq1[j2][0], bq1[j2][2]);
                    mma_s8(d2[i][j2 * 2 + 1], aq0[i], bq1[j2][1], bq1[j2][3]);
                }
        }
        __syncthreads();
    }

    const int q = lane >> 2;
    const int cpair = (lane & 3) * 2;
    #pragma unroll
    for (int i = 0; i < 2; ++i) {
        int gr0 = mBase + wm * 32 + i * 16 + q;
        float sa0 = (gr0 < M) ? As[gr0] : 0.f;
        float sa1 = (gr0 + 8 < M) ? As[gr0 + 8] : 0.f;
        #pragma unroll
        for (int j = 0; j < 4; ++j) {
            int gc = nBase + wn * 32 + j * 8 + cpair;
            float sb0 = Bs[gc], sb1 = Bs[gc + 1];
            if (gr0 < M) {
                float v0 = sa0 * sb0 * recomb(d1[i][j][0], d2[i][j][0]);
                float v1 = sa0 * sb1 * recomb(d1[i][j][1], d2[i][j][1]);
                *(float2*)(C + (size_t)gr0 * ldc + gc) = make_float2(v0, v1);
            }
            if (gr0 + 8 < M) {
                float v2 = sa1 * sb0 * recomb(d1[i][j][2], d2[i][j][2]);
                float v3 = sa1 * sb1 * recomb(d1[i][j][3], d2[i][j][3]);
                *(float2*)(C + (size_t)(gr0 + 8) * ldc + gc) = make_float2(v2, v3);
            }
        }
    }
}

// ============================================================================
// Edge int8 GEMM: acc[row[e], :] += x[col[e], :] @ W_r^T
// Epilogue: stage tile into smem (rotated), then red.global.add.v4.f32
// ============================================================================
__global__ __launch_bounds__(512, 1)
void egemm_s8(int K,
              const int8_t* __restrict__ Aq1, const int8_t* __restrict__ Aq0,
              const float* __restrict__ As,
              const int8_t* __restrict__ Wq1, const int8_t* __restrict__ Wq0,
              const float* __restrict__ Wsc,
              float* __restrict__ acc)
{
    extern __shared__ char sm[];
    __shared__ int s_ecol[128];
    __shared__ int s_erow[128];
    __shared__ float s_sa[128];
    __shared__ float s_sb[128];
    const uint32_t sbase = smem_u32(sm);

    const int bid = blockIdx.x;
    if (bid >= g_tilestart[NREL]) return;
    int r = 0;
    #pragma unroll
    for (int i = 0; i < NREL - 1; ++i)
        if (bid >= g_tilestart[i + 1]) r = i + 1;
    const int tile = bid - g_tilestart[r];
    const int estart = g_off[r] + tile * 128;
    const int medge = min(128, g_off[r + 1] - estart);

    const int tid  = threadIdx.x;
    const int wid  = tid >> 5;
    const int lane = tid & 31;
    const int wm   = wid & 3;
    const int wn   = wid >> 2;

    const float* Bs = Wsc + r * DHID;
    if (tid < 128) {
        bool ok = tid < medge;
        int c = ok ? g_ecol_s[estart + tid] : 0;
        s_ecol[tid] = c;
        s_erow[tid] = ok ? g_erow_s[estart + tid] : -1;
        s_sa[tid] = As[c];
        s_sb[tid] = Bs[tid];
    }
    __syncthreads();

    const int8_t* Bq1 = Wq1 + (size_t)r * DHID * K;
    const int8_t* Bq0 = Wq0 + (size_t)r * DHID * K;

    int d1[2][4][4], d2[2][4][4];
    #pragma unroll
    for (int i = 0; i < 2; ++i)
        #pragma unroll
        for (int j = 0; j < 4; ++j)
            #pragma unroll
            for (int t = 0; t < 4; ++t) { d1[i][j][t] = 0; d2[i][j][t] = 0; }

    const int nk = K >> 6;

    auto issue = [&](int s, int k0) {
        const uint32_t sb = sbase + (uint32_t)s * STAGE8;
        int row = tid >> 2;
        int seg = tid & 3;
        uint32_t so = sw_off(row, seg);
        size_t aoff = (size_t)s_ecol[row] * K + k0 + seg * 16;
        cp16(sb + so,             Aq1 + aoff, 16);
        cp16(sb + TILE8 + so,     Aq0 + aoff, 16);
        size_t boff = (size_t)row * K + k0 + seg * 16;
        cp16(sb + 2 * TILE8 + so, Bq1 + boff, 16);
        cp16(sb + 3 * TILE8 + so, Bq0 + boff, 16);
    };

    issue(0, 0);
    CP_COMMIT();

    for (int c = 0; c < nk; ++c) {
        if (c + 1 < nk) {
            issue((c + 1) & 1, (c + 1) << 6);
            CP_COMMIT();
            cp_wait<1>();
        } else {
            cp_wait<0>();
        }
        __syncthreads();

        const uint32_t bA1 = sbase + (uint32_t)(c & 1) * STAGE8;
        const uint32_t bA0 = bA1 + TILE8;
        const uint32_t bB1 = bA1 + 2 * TILE8;
        const uint32_t bB0 = bA1 + 3 * TILE8;

        #pragma unroll
        for (int ks = 0; ks < 2; ++ks) {
            uint32_t aq1[2][4], aq0[2][4], bq1[2][4], bq0[2][4];
            #pragma unroll
            for (int i = 0; i < 2; ++i) {
                uint32_t ad = lds_addr(0, wm * 32 + i * 16, ks, lane);
                ldsm4(aq1[i], bA1 + ad);
                ldsm4(aq0[i], bA0 + ad);
            }
            #pragma unroll
            for (int j2 = 0; j2 < 2; ++j2) {
                uint32_t bd = lds_addr(0, wn * 32 + j2 * 16, ks, lane);
                ldsm4(bq1[j2], bB1 + bd);
                ldsm4(bq0[j2], bB0 + bd);
            }
            #pragma unroll
            for (int i = 0; i < 2; ++i)
                #pragma unroll
                for (int j2 = 0; j2 < 2; ++j2) {
                    mma_s8(d1[i][j2 * 2],     aq1[i], bq1[j2][0], bq1[j2][2]);
                    mma_s8(d1[i][j2 * 2 + 1], aq1[i], bq1[j2][1], bq1[j2][3]);
                    mma_s8(d2[i][j2 * 2],     aq1[i], bq0[j2][0], bq0[j2][2]);
                    mma_s8(d2[i][j2 * 2 + 1], aq1[i], bq0[j2][1], bq0[j2][3]);
                    mma_s8(d2[i][j2 * 2],     aq0[i], bq1[j2][0], bq1[j2][2]);
                    mma_s8(d2[i][j2 * 2 + 1], aq0[i], bq1[j2][1], bq1[j2][3]);
                }
        }
        __syncthreads();
    }

    // ---- phase 1: stage raw tile values into smem, rotated cols ----
    float* F = (float*)sm;
    const int q = lane >> 2;
    const int cpair = (lane & 3) * 2;
    #pragma unroll
    for (int i = 0; i < 2; ++i) {
        int r0 = wm * 32 + i * 16 + q;
        int r1 = r0 + 8;
        #pragma unroll
        for (int j = 0; j < 4; ++j) {
            int c = wn * 32 + j * 8 + cpair;
            int p0 = (c + r0 * 8) & 127;
            int p1 = (c + r1 * 8) & 127;
            *(float2*)(F + r0 * 128 + p0) =
                make_float2(recomb(d1[i][j][0], d2[i][j][0]), recomb(d1[i][j][1], d2[i][j][1]));
            *(float2*)(F + r1 * 128 + p1) =
                make_float2(recomb(d1[i][j][2], d2[i][j][2]), recomb(d1[i][j][3], d2[i][j][3]));
        }
    }
    __syncthreads();

    // ---- phase 2: vectorized atomic scatter ----
    {
        int row = tid >> 2;
        int gr = s_erow[row];
        if (gr >= 0) {
            float sa = s_sa[row];
            int quarter = tid & 3;
            float* dst = acc + (size_t)gr * DHID;
            #pragma unroll
            for (int k2 = 0; k2 < 8; ++k2) {
                int c0 = quarter * 32 + k2 * 4;
                int phys = (c0 + row * 8) & 127;
                float4 v = *(float4*)(F + row * 128 + phys);
                float4 sb4 = *(float4*)(s_sb + c0);
                red_add4(dst + c0, sa * sb4.x * v.x, sa * sb4.y * v.y,
                                   sa * sb4.z * v.z, sa * sb4.w * v.w);
            }
        }
    }
}

// ---------------- edge sort (counting sort by relation) ----------------
__global__ void zero16() {
    if (threadIdx.x < NREL) g_cnt[threadIdx.x] = 0;
}
__global__ void hist_k(const int* __restrict__ et) {
    __shared__ int h[NREL];
    if (threadIdx.x < NREL) h[threadIdx.x] = 0;
    __syncthreads();
    int i = blockIdx.x * 256 + threadIdx.x;
    if (i < NEDGE) atomicAdd(&h[et[i]], 1);
    __syncthreads();
    if (threadIdx.x < NREL && h[threadIdx.x]) atomicAdd(&g_cnt[threadIdx.x], h[threadIdx.x]);
}
__global__ void prefix_k() {
    int o = 0, t = 0;
    for (int r = 0; r < NREL; ++r) {
        g_off[r] = o; g_cursor[r] = o; g_tilestart[r] = t;
        o += g_cnt[r]; t += (g_cnt[r] + 127) >> 7;
    }
    g_off[NREL] = o; g_tilestart[NREL] = t;
}
__global__ void scatter_k(const int* __restrict__ er, const int* __restrict__ ec,
                          const int* __restrict__ et) {
    __shared__ int h[NREL], base[NREL];
    if (threadIdx.x < NREL) h[threadIdx.x] = 0;
    __syncthreads();
    int i = blockIdx.x * 256 + threadIdx.x;
    int t = 0, my = 0;
    bool ok = i < NEDGE;
    if (ok) { t = et[i]; my = atomicAdd(&h[t], 1); }
    __syncthreads();
    if (threadIdx.x < NREL && h[threadIdx.x])
        base[threadIdx.x] = atomicAdd(&g_cursor[threadIdx.x], h[threadIdx.x]);
    __syncthreads();
    if (ok) {
        int p = base[t] + my;
        g_erow_s[p] = er[i];
        g_ecol_s[p] = ec[i];
    }
}

// ---------------- quantize entity embeddings (K=256, warp per row) ----------------
__global__ void quantE(const float* __restrict__ E,
                       int8_t* __restrict__ q1, int8_t* __restrict__ q0,
                       float* __restrict__ s) {
    int row = blockIdx.x * 8 + (threadIdx.x >> 5);
    if (row >= N_NODES) return;
    int lane = threadIdx.x & 31;
    const float* rp_ = E + (size_t)row * DEMB;
    float4 v0 = ((const float4*)rp_)[lane * 2];
    float4 v1 = ((const float4*)rp_)[lane * 2 + 1];
    float mx = fmaxf(fmaxf(fmaxf(fabsf(v0.x), fabsf(v0.y)), fmaxf(fabsf(v0.z), fabsf(v0.w))),
                     fmaxf(fmaxf(fabsf(v1.x), fabsf(v1.y)), fmaxf(fabsf(v1.z), fabsf(v1.w))));
    #pragma unroll
    for (int o = 16; o; o >>= 1) mx = fmaxf(mx, __shfl_xor_sync(0xFFFFFFFFu, mx, o));
    mx = fmaxf(mx, 1e-35f);
    float inv = 16256.f / mx;
    int h[8], l[8];
    quant1(v0.x, inv, h[0], l[0]); quant1(v0.y, inv, h[1], l[1]);
    quant1(v0.z, inv, h[2], l[2]); quant1(v0.w, inv, h[3], l[3]);
    quant1(v1.x, inv, h[4], l[4]); quant1(v1.y, inv, h[5], l[5]);
    quant1(v1.z, inv, h[6], l[6]); quant1(v1.w, inv, h[7], l[7]);
    uint32_t* p1 = (uint32_t*)(q1 + (size_t)row * DEMB);
    uint32_t* p0 = (uint32_t*)(q0 + (size_t)row * DEMB);
    p1[lane * 2]     = pack4i8(h[0], h[1], h[2], h[3]);
    p1[lane * 2 + 1] = pack4i8(h[4], h[5], h[6], h[7]);
    p0[lane * 2]     = pack4i8(l[0], l[1], l[2], l[3]);
    p0[lane * 2 + 1] = pack4i8(l[4], l[5], l[6], l[7]);
    if (lane == 0) s[row] = mx * (1.f / 16256.f);
}

// ---------------- quantized relation weights W_r^T: grid NREL*DHID, block din ----------------
__global__ void build_wrT_q(const float* __restrict__ bases,
                            const float* __restrict__ coeff,
                            int8_t* __restrict__ q1, int8_t* __restrict__ q0,
                            float* __restrict__ sc, int din) {
    __shared__ float red_[256];
    int bid = blockIdx.x;
    int r = bid >> 7;
    int n = bid & 127;
    int k = threadIdx.x;
    float v = 0.f;
    #pragma unroll
    for (int b = 0; b < NBAS; ++b)
        v += coeff[r * NBAS + b] * bases[((size_t)b * din + k) * DHID + n];
    red_[k] = fabsf(v);
    __syncthreads();
    for (int s = blockDim.x >> 1; s > 0; s >>= 1) {
        if (k < s) red_[k] = fmaxf(red_[k], red_[k + s]);
        __syncthreads();
    }
    float mx = fmaxf(red_[0], 1e-35f);
    float inv = 16256.f / mx;
    int h, l;
    quant1(v, inv, h, l);
    size_t o = (size_t)bid * din + k;
    q1[o] = (int8_t)h;
    q0[o] = (int8_t)l;
    if (k == 0) sc[bid] = mx * (1.f / 16256.f);
}

// ---------------- quantized selfw^T: grid DHID, block din ----------------
__global__ void build_selfT_q(const float* __restrict__ selfw,
                              int8_t* __restrict__ q1, int8_t* __restrict__ q0,
                              float* __restrict__ sc, int din) {
    __shared__ float red_[256];
    int n = blockIdx.x;
    int k = threadIdx.x;
    float v = selfw[(size_t)k * DHID + n];
    red_[k] = fabsf(v);
    __syncthreads();
    for (int s = blockDim.x >> 1; s > 0; s >>= 1) {
        if (k < s) red_[k] = fmaxf(red_[k], red_[k + s]);
        __syncthreads();
    }
    float mx = fmaxf(red_[0], 1e-35f);
    float inv = 16256.f / mx;
    int h, l;
    quant1(v, inv, h, l);
    size_t o = (size_t)n * din + k;
    q1[o] = (int8_t)h;
    q0[o] = (int8_t)l;
    if (k == 0) sc[n] = mx * (1.f / 16256.f);
}

// ---------------- quantized combined w1 head|tail transposed: grid 256, block 128 ----------------
__global__ void build_w1c_q(const float* __restrict__ w1,
                            int8_t* __restrict__ q1, int8_t* __restrict__ q0,
                            float* __restrict__ sc) {
    __shared__ float red_[128];
    int n = blockIdx.x;
    int k = threadIdx.x;
    float v = (n < DHID) ? w1[(size_t)k * DHID + n]
                         : w1[(size_t)(384 + k) * DHID + (n - DHID)];
    red_[k] = fabsf(v);
    __syncthreads();
    for (int s = 64; s > 0; s >>= 1) {
        if (k < s) red_[k] = fmaxf(red_[k], red_[k + s]);
        __syncthreads();
    }
    float mx = fmaxf(red_[0], 1e-35f);
    float inv = 16256.f / mx;
    int h, l;
    quant1(v, inv, h, l);
    size_t o = (size_t)n * DHID + k;
    q1[o] = (int8_t)h;
    q0[o] = (int8_t)l;
    if (k == 0) sc[n] = mx * (1.f / 16256.f);
}

// ---------------- relu + layernorm -> quantized int8 hi/lo ----------------
__global__ void relu_ln_q(const float* __restrict__ acc,
                          const float* __restrict__ gamma,
                          const float* __restrict__ beta,
                          int8_t* __restrict__ xq1, int8_t* __restrict__ xq0,
                          float* __restrict__ xs) {
    int n = blockIdx.x * 8 + (threadIdx.x >> 5);
    if (n >= N_NODES) return;
    int lane = threadIdx.x & 31;
    float4 v = ((const float4*)(acc + (size_t)n * DHID))[lane];
    v.x = fmaxf(v.x, 0.f); v.y = fmaxf(v.y, 0.f);
    v.z = fmaxf(v.z, 0.f); v.w = fmaxf(v.w, 0.f);
    float s = v.x + v.y + v.z + v.w;
    #pragma unroll
    for (int o = 16; o; o >>= 1) s += __shfl_xor_sync(0xFFFFFFFFu, s, o);
    float mu = s * (1.f / DHID);
    float dx = v.x - mu, dy = v.y - mu, dz = v.z - mu, dw = v.w - mu;
    float ss = dx * dx + dy * dy + dz * dz + dw * dw;
    #pragma unroll
    for (int o = 16; o; o >>= 1) ss += __shfl_xor_sync(0xFFFFFFFFu, ss, o);
    float invs = rsqrtf(ss * (1.f / DHID) + 1e-5f);
    float4 g = ((const float4*)gamma)[lane];
    float4 b = ((const float4*)beta)[lane];
    float ox = dx * invs * g.x + b.x;
    float oy = dy * invs * g.y + b.y;
    float oz = dz * invs * g.z + b.z;
    float ow = dw * invs * g.w + b.w;
    float mx = fmaxf(fmaxf(fabsf(ox), fabsf(oy)), fmaxf(fabsf(oz), fabsf(ow)));
    #pragma unroll
    for (int o = 16; o; o >>= 1) mx = fmaxf(mx, __shfl_xor_sync(0xFFFFFFFFu, mx, o));
    mx = fmaxf(mx, 1e-35f);
    float inv = 16256.f / mx;
    int h0, h1, h2, h3, l0, l1, l2, l3;
    quant1(ox, inv, h0, l0); quant1(oy, inv, h1, l1);
    quant1(oz, inv, h2, l2); quant1(ow, inv, h3, l3);
    ((uint32_t*)(xq1 + (size_t)n * DHID))[lane] = pack4i8(h0, h1, h2, h3);
    ((uint32_t*)(xq0 + (size_t)n * DHID))[lane] = pack4i8(l0, l1, l2, l3);
    if (lane == 0) xs[n] = mx * (1.f / 16256.f);
}

// ---------------- relproj: block per relation, coalesced w1 ----------------
__global__ void relproj_k(const float* __restrict__ relemb,
                          const float* __restrict__ w1,
                          const float* __restrict__ b1,
                          float* __restrict__ rp) {
    __shared__ float s_e[DEMB];
    int r = blockIdx.x;
    int j = threadIdx.x;
    for (int i = j; i < DEMB; i += DHID) s_e[i] = relemb[r * DEMB + i];
    __syncthreads();
    float s = b1[j];
    #pragma unroll 4
    for (int i = 0; i < DEMB; ++i)
        s = fmaf(s_e[i], w1[(size_t)(DHID + i) * DHID + j], s);
    rp[r * DHID + j] = s;
}

// ---------------- score ----------------
__global__ void score_k(const int* __restrict__ head,
                        const int* __restrict__ rel,
                        const int* __restrict__ tail,
                        const float* __restrict__ HPTP,
                        const float* __restrict__ rp,
                        const float* __restrict__ w2,
                        const float* __restrict__ b2,
                        float* __restrict__ out) {
    int q = blockIdx.x * 8 + (threadIdx.x >> 5);
    if (q >= NQUERY) return;
    int lane = threadIdx.x & 31;
    int h = head[q], r = rel[q], t = tail[q];
    float4 a = ((const float4*)(HPTP + (size_t)h * 256))[lane];
    float4 bb = ((const float4*)(HPTP + (size_t)t * 256 + DHID))[lane];
    float4 c = ((const float4*)(rp + (size_t)r * DHID))[lane];
    float4 w = ((const float4*)w2)[lane];
    float s = fmaxf(a.x + bb.x + c.x, 0.f) * w.x
            + fmaxf(a.y + bb.y + c.y, 0.f) * w.y
            + fmaxf(a.z + bb.z + c.z, 0.f) * w.z
            + fmaxf(a.w + bb.w + c.w, 0.f) * w.w;
    #pragma unroll
    for (int o = 16; o; o >>= 1) s += __shfl_xor_sync(0xFFFFFFFFu, s, o);
    if (lane == 0) out[q] = s + b2[0];
}

// ---------------- launch ----------------
extern "C" void kernel_launch(void* const* d_in, const int* in_sizes, int n_in,
                              void* d_out, int out_size) {
    (void)in_sizes; (void)n_in; (void)out_size;
    const int*   edge_index   = (const int*)d_in[0];
    const int*   edge_type    = (const int*)d_in[1];
    const int*   head_ids     = (const int*)d_in[2];
    const int*   relation_ids = (const int*)d_in[3];
    const int*   tail_ids     = (const int*)d_in[4];
    const float* entity_emb   = (const float*)d_in[5];
    const float* relation_emb = (const float*)d_in[6];
    const float* bases0       = (const float*)d_in[7];
    const float* coeff0       = (const float*)d_in[8];
    const float* selfw0       = (const float*)d_in[9];
    const float* bases1       = (const float*)d_in[10];
    const float* coeff1       = (const float*)d_in[11];
    const float* selfw1       = (const float*)d_in[12];
    const float* ln0_g        = (const float*)d_in[13];
    const float* ln0_b        = (const float*)d_in[14];
    const float* ln1_g        = (const float*)d_in[15];
    const float* ln1_b        = (const float*)d_in[16];
    const float* w1           = (const float*)d_in[17];
    const float* b1           = (const float*)d_in[18];
    const float* w2           = (const float*)d_in[19];
    const float* b2           = (const float*)d_in[20];
    float* out = (float*)d_out;

    int8_t *Eq1, *Eq0, *Wq1, *Wq0, *Sq1, *Sq0, *xq1, *xq0, *w1q1, *w1q0;
    float *Es, *Wsc, *Ssc, *xs, *w1sc, *acc, *HPTP, *rp;
    cudaGetSymbolAddress((void**)&Eq1, g_Eq1);
    cudaGetSymbolAddress((void**)&Eq0, g_Eq0);
    cudaGetSymbolAddress((void**)&Es,  g_Es);
    cudaGetSymbolAddress((void**)&Wq1, g_Wq1);
    cudaGetSymbolAddress((void**)&Wq0, g_Wq0);
    cudaGetSymbolAddress((void**)&Wsc, g_Wsc);
    cudaGetSymbolAddress((void**)&Sq1, g_Sq1);
    cudaGetSymbolAddress((void**)&Sq0, g_Sq0);
    cudaGetSymbolAddress((void**)&Ssc, g_Ssc);
    cudaGetSymbolAddress((void**)&xq1, g_xq1);
    cudaGetSymbolAddress((void**)&xq0, g_xq0);
    cudaGetSymbolAddress((void**)&xs,  g_xs);
    cudaGetSymbolAddress((void**)&w1q1, g_w1q1);
    cudaGetSymbolAddress((void**)&w1q0, g_w1q0);
    cudaGetSymbolAddress((void**)&w1sc, g_w1sc);
    cudaGetSymbolAddress((void**)&acc,  g_acc);
    cudaGetSymbolAddress((void**)&HPTP, g_HPTP);
    cudaGetSymbolAddress((void**)&rp,   g_rp);

    cudaFuncSetAttribute(gemm_s8,  cudaFuncAttributeMaxDynamicSharedMemorySize, SMEM8);
    cudaFuncSetAttribute(egemm_s8, cudaFuncAttributeMaxDynamicSharedMemorySize, SMEM8);

    const int* erow = edge_index;
    const int* ecol = edge_index + NEDGE;
    const int nM = (N_NODES + 127) / 128;   // 391

    // ----- edge sort by relation -----
    zero16<<<1, 32>>>();
    hist_k<<<(NEDGE + 255) / 256, 256>>>(edge_type);
    prefix_k<<<1, 1>>>();
    scatter_k<<<(NEDGE + 255) / 256, 256>>>(erow, ecol, edge_type);

    // ----- layer 0 -----
    quantE<<<(N_NODES + 7) / 8, 256>>>(entity_emb, Eq1, Eq0, Es);
    build_wrT_q<<<NREL * DHID, DEMB>>>(bases0, coeff0, Wq1, Wq0, Wsc, DEMB);
    build_selfT_q<<<DHID, DEMB>>>(selfw0, Sq1, Sq0, Ssc, DEMB);
    gemm_s8<<<dim3(1, nM), 512, SMEM8>>>(N_NODES, DEMB, Eq1, Eq0, Es, Sq1, Sq0, Ssc, acc, DHID);
    egemm_s8<<<EGRID, 512, SMEM8>>>(DEMB, Eq1, Eq0, Es, Wq1, Wq0, Wsc, acc);
    relu_ln_q<<<(N_NODES + 7) / 8, 256>>>(acc, ln0_g, ln0_b, xq1, xq0, xs);

    // ----- layer 1 -----
    build_wrT_q<<<NREL * DHID, DHID>>>(bases1, coeff1, Wq1, Wq0, Wsc, DHID);
    build_selfT_q<<<DHID, DHID>>>(selfw1, Sq1, Sq0, Ssc, DHID);
    gemm_s8<<<dim3(1, nM), 512, SMEM8>>>(N_NODES, DHID, xq1, xq0, xs, Sq1, Sq0, Ssc, acc, DHID);
    egemm_s8<<<EGRID, 512, SMEM8>>>(DHID, xq1, xq0, xs, Wq1, Wq0, Wsc, acc);
    relu_ln_q<<<(N_NODES + 7) / 8, 256>>>(acc, ln1_g, ln1_b, xq1, xq0, xs);

    // ----- scoring -----
    relproj_k<<<NREL, DHID>>>(relation_emb, w1, b1, rp);
    build_w1c_q<<<2 * DHID, DHID>>>(w1, w1q1, w1q0, w1sc);
    gemm_s8<<<dim3(2, nM), 512, SMEM8>>>(N_NODES, DHID, xq1, xq0, xs, w1q1, w1q0, w1sc, HPTP, 256);
    score_k<<<(NQUERY + 7) / 8, 256>>>(head_ids, relation_ids, tail_ids, HPTP, rp, w2, b2, out);
}

// round 9
// speedup vs baseline: 1.1583x; 1.1583x over previous
#include <cuda_runtime.h>
#include <cuda_bf16.h>
#include <cstdint>

#define N_NODES 50000
#define NREL    16
#define NBAS    16
#define DEMB    256
#define DHID    128
#define NEDGE   300000
#define NQUERY  100000
#define EGRID   ((NEDGE + 127) / 128 + 16)

// ---------------- scratch (static __device__ globals; no allocation) ----------------
__device__ int8_t g_Eq1[(size_t)N_NODES * DEMB];
__device__ int8_t g_Eq0[(size_t)N_NODES * DEMB];
__device__ float  g_Es[N_NODES];
__device__ int8_t g_Wq1[(size_t)NREL * DHID * DEMB];
__device__ int8_t g_Wq0[(size_t)NREL * DHID * DEMB];
__device__ float  g_Wsc[NREL * DHID];
__device__ int8_t g_Sq1[DHID * DEMB];
__device__ int8_t g_Sq0[DHID * DEMB];
__device__ float  g_Ssc[DHID];
__device__ int8_t g_xq1[N_NODES * DHID];
__device__ int8_t g_xq0[N_NODES * DHID];
__device__ float  g_xs[N_NODES];
__device__ int8_t g_w1q1[2 * DHID * DHID];
__device__ int8_t g_w1q0[2 * DHID * DHID];
__device__ float  g_w1sc[2 * DHID];
__device__ float g_acc[N_NODES * DHID];
__device__ float g_HPTP[(size_t)N_NODES * 2 * DHID];
__device__ float g_rp[NREL * DHID];
// edge sort
__device__ int g_cnt[NREL];
__device__ int g_off[NREL + 1];
__device__ int g_tilestart[NREL + 1];
__device__ int g_cursor[NREL];
__device__ int g_erow_s[NEDGE];
__device__ int g_ecol_s[NEDGE];

__device__ __forceinline__ uint32_t smem_u32(const void* p) {
    uint32_t a;
    asm("{ .reg .u64 t; cvta.to.shared.u64 t, %1; cvt.u32.u64 %0, t; }" : "=r"(a) : "l"(p));
    return a;
}
__device__ __forceinline__ void ldsm4(uint32_t* r, uint32_t addr) {
    asm volatile("ldmatrix.sync.aligned.m8n8.x4.shared.b16 {%0,%1,%2,%3}, [%4];"
                 : "=r"(r[0]), "=r"(r[1]), "=r"(r[2]), "=r"(r[3]) : "r"(addr));
}
__device__ __forceinline__ void mma_s8(int* d, const uint32_t* a, uint32_t b0, uint32_t b1) {
    asm volatile(
        "mma.sync.aligned.m16n8k32.row.col.s32.s8.s8.s32 "
        "{%0,%1,%2,%3}, {%4,%5,%6,%7}, {%8,%9}, {%0,%1,%2,%3};"
        : "+r"(d[0]), "+r"(d[1]), "+r"(d[2]), "+r"(d[3])
        : "r"(a[0]), "r"(a[1]), "r"(a[2]), "r"(a[3]), "r"(b0), "r"(b1));
}
__device__ __forceinline__ void cp16(uint32_t dst, const void* src, int srcBytes) {
    asm volatile("cp.async.cg.shared.global [%0], [%1], 16, %2;"
                 :: "r"(dst), "l"(src), "r"(srcBytes));
}
#define CP_COMMIT() asm volatile("cp.async.commit_group;" ::: "memory")
template<int Nw> __device__ __forceinline__ void cp_wait() {
    asm volatile("cp.async.wait_group %0;" :: "n"(Nw) : "memory");
}
__device__ __forceinline__ void red_add2(float* p, float a, float b) {
    asm volatile("red.global.add.v2.f32 [%0], {%1,%2};"
                 :: "l"(p), "f"(a), "f"(b) : "memory");
}
__device__ __forceinline__ uint32_t pack4i8(int a, int b, int c, int d) {
    return (uint32_t)(a & 0xff) | ((uint32_t)(b & 0xff) << 8) |
           ((uint32_t)(c & 0xff) << 16) | ((uint32_t)(d & 0xff) << 24);
}
__device__ __forceinline__ void quant1(float v, float inv, int& h, int& l) {
    float q = v * inv;                       // |q| <= 16256
    h = __float2int_rn(q * (1.f / 128.f));
    l = __float2int_rn(q - 128.f * (float)h);
}
__device__ __forceinline__ float recomb(int d1, int d2) {
    return fmaf(128.f, (float)d2, 16384.f * (float)d1);
}

#define TILE8  8192                   // 128 rows x 64 bytes
#define STAGE8 (4 * TILE8)            // 32 KB
#define SMEM8  (2 * STAGE8)           // 64 KB

// smem addressing: 64B rows, 4x16B segs, swizzle seg ^= (row>>1)&3
__device__ __forceinline__ uint32_t sw_off(int row, int seg) {
    return (uint32_t)(row * 64) + ((uint32_t)(seg ^ ((row >> 1) & 3)) << 4);
}
__device__ __forceinline__ uint32_t lds_addr(uint32_t tb, int row0, int ks, int lane) {
    int row = row0 + (lane & 7) + ((lane >> 3) & 1) * 8;
    int seg = ks * 2 + (lane >> 4);
    return tb + sw_off(row, seg);
}

// ============================================================================
// Dense int8 GEMM: C[M,N] = (Aq,As) @ (Bq,Bs)^T ; grid (N/128, ceil(M/128)), 512 thr
// ============================================================================
__global__ __launch_bounds__(512, 1)
void gemm_s8(int M, int K,
             const int8_t* __restrict__ Aq1, const int8_t* __restrict__ Aq0,
             const float* __restrict__ As,
             const int8_t* __restrict__ Bq1, const int8_t* __restrict__ Bq0,
             const float* __restrict__ Bs,
             float* __restrict__ C, int ldc)
{
    extern __shared__ char sm[];
    const uint32_t sbase = smem_u32(sm);
    const int tid  = threadIdx.x;
    const int wid  = tid >> 5;
    const int lane = tid & 31;
    const int wm   = wid & 3;
    const int wn   = wid >> 2;
    const int mBase = blockIdx.y * 128;
    const int nBase = blockIdx.x * 128;

    int d1[2][4][4], d2[2][4][4];
    #pragma unroll
    for (int i = 0; i < 2; ++i)
        #pragma unroll
        for (int j = 0; j < 4; ++j)
            #pragma unroll
            for (int t = 0; t < 4; ++t) { d1[i][j][t] = 0; d2[i][j][t] = 0; }

    const int nk = K >> 6;

    auto issue = [&](int s, int k0) {
        const uint32_t sb = sbase + (uint32_t)s * STAGE8;
        int row = tid >> 2;
        int seg = tid & 3;
        uint32_t so = sw_off(row, seg);
        int gr = mBase + row;
        int okA = (gr < M) ? 16 : 0;
        size_t aoff = (size_t)(okA ? gr : 0) * K + k0 + seg * 16;
        cp16(sb + so,             Aq1 + aoff, okA);
        cp16(sb + TILE8 + so,     Aq0 + aoff, okA);
        size_t boff = (size_t)(nBase + row) * K + k0 + seg * 16;
        cp16(sb + 2 * TILE8 + so, Bq1 + boff, 16);
        cp16(sb + 3 * TILE8 + so, Bq0 + boff, 16);
    };

    issue(0, 0);
    CP_COMMIT();

    for (int c = 0; c < nk; ++c) {
        if (c + 1 < nk) {
            issue((c + 1) & 1, (c + 1) << 6);
            CP_COMMIT();
            cp_wait<1>();
        } else {
            cp_wait<0>();
        }
        __syncthreads();

        const uint32_t bA1 = sbase + (uint32_t)(c & 1) * STAGE8;
        const uint32_t bA0 = bA1 + TILE8;
        const uint32_t bB1 = bA1 + 2 * TILE8;
        const uint32_t bB0 = bA1 + 3 * TILE8;

        #pragma unroll
        for (int ks = 0; ks < 2; ++ks) {
            uint32_t aq1[2][4], aq0[2][4], bq1[2][4], bq0[2][4];
            #pragma unroll
            for (int i = 0; i < 2; ++i) {
                uint32_t ad = lds_addr(0, wm * 32 + i * 16, ks, lane);
                ldsm4(aq1[i], bA1 + ad);
                ldsm4(aq0[i], bA0 + ad);
            }
            #pragma unroll
            for (int j2 = 0; j2 < 2; ++j2) {
                uint32_t bd = lds_addr(0, wn * 32 + j2 * 16, ks, lane);
                ldsm4(bq1[j2], bB1 + bd);
                ldsm4(bq0[j2], bB0 + bd);
            }
            #pragma unroll
            for (int i = 0; i < 2; ++i)
                #pragma unroll
                for (int j2 = 0; j2 < 2; ++j2) {
                    mma_s8(d1[i][j2 * 2],     aq1[i], bq1[j2][0], bq1[j2][2]);
                    mma_s8(d1[i][j2 * 2 + 1], aq1[i], bq1[j2][1], bq1[j2][3]);
                    mma_s8(d2[i][j2 * 2],     aq1[i], bq0[j2][0], bq0[j2][2]);
                    mma_s8(d2[i][j2 * 2 + 1], aq1[i], bq0[j2][1], bq0[j2][3]);
                    mma_s8(d2[i][j2 * 2],     aq0[i], bq1[j2][0], bq1[j2][2]);
                    mma_s8(d2[i][j2 * 2 + 1], aq0[i], bq1[j2][1], bq1[j2][3]);
                }
        }
        __syncthreads();
    }

    const int q = lane >> 2;
    const int cpair = (lane & 3) * 2;
    #pragma unroll
    for (int i = 0; i < 2; ++i) {
        int gr0 = mBase + wm * 32 + i * 16 + q;
        float sa0 = (gr0 < M) ? As[gr0] : 0.f;
        float sa1 = (gr0 + 8 < M) ? As[gr0 + 8] : 0.f;
        #pragma unroll
        for (int j = 0; j < 4; ++j) {
            int gc = nBase + wn * 32 + j * 8 + cpair;
            float sb0 = Bs[gc], sb1 = Bs[gc + 1];
            if (gr0 < M) {
                float v0 = sa0 * sb0 * recomb(d1[i][j][0], d2[i][j][0]);
                float v1 = sa0 * sb1 * recomb(d1[i][j][1], d2[i][j][1]);
                *(float2*)(C + (size_t)gr0 * ldc + gc) = make_float2(v0, v1);
            }
            if (gr0 + 8 < M) {
                float v2 = sa1 * sb0 * recomb(d1[i][j][2], d2[i][j][2]);
                float v3 = sa1 * sb1 * recomb(d1[i][j][3], d2[i][j][3]);
                *(float2*)(C + (size_t)(gr0 + 8) * ldc + gc) = make_float2(v2, v3);
            }
        }
    }
}

// ============================================================================
// Edge int8 GEMM: acc[row[e], :] += x[col[e], :] @ W_r^T
// Epilogue: red.global.add.v2.f32 straight from accumulator registers
// ============================================================================
__global__ __launch_bounds__(512, 1)
void egemm_s8(int K,
              const int8_t* __restrict__ Aq1, const int8_t* __restrict__ Aq0,
              const float* __restrict__ As,
              const int8_t* __restrict__ Wq1, const int8_t* __restrict__ Wq0,
              const float* __restrict__ Wsc,
              float* __restrict__ acc)
{
    extern __shared__ char sm[];
    __shared__ int s_ecol[128];
    __shared__ int s_erow[128];
    __shared__ float s_sa[128];
    const uint32_t sbase = smem_u32(sm);

    const int bid = blockIdx.x;
    if (bid >= g_tilestart[NREL]) return;
    int r = 0;
    #pragma unroll
    for (int i = 0; i < NREL - 1; ++i)
        if (bid >= g_tilestart[i + 1]) r = i + 1;
    const int tile = bid - g_tilestart[r];
    const int estart = g_off[r] + tile * 128;
    const int medge = min(128, g_off[r + 1] - estart);

    const int tid  = threadIdx.x;
    const int wid  = tid >> 5;
    const int lane = tid & 31;
    const int wm   = wid & 3;
    const int wn   = wid >> 2;

    if (tid < 128) {
        bool ok = tid < medge;
        int c = ok ? g_ecol_s[estart + tid] : 0;
        s_ecol[tid] = c;
        s_erow[tid] = ok ? g_erow_s[estart + tid] : -1;
        s_sa[tid] = As[c];
    }
    __syncthreads();

    const int8_t* Bq1 = Wq1 + (size_t)r * DHID * K;
    const int8_t* Bq0 = Wq0 + (size_t)r * DHID * K;
    const float*  Bs  = Wsc + r * DHID;

    int d1[2][4][4], d2[2][4][4];
    #pragma unroll
    for (int i = 0; i < 2; ++i)
        #pragma unroll
        for (int j = 0; j < 4; ++j)
            #pragma unroll
            for (int t = 0; t < 4; ++t) { d1[i][j][t] = 0; d2[i][j][t] = 0; }

    const int nk = K >> 6;

    auto issue = [&](int s, int k0) {
        const uint32_t sb = sbase + (uint32_t)s * STAGE8;
        int row = tid >> 2;
        int seg = tid & 3;
        uint32_t so = sw_off(row, seg);
        size_t aoff = (size_t)s_ecol[row] * K + k0 + seg * 16;
        cp16(sb + so,             Aq1 + aoff, 16);
        cp16(sb + TILE8 + so,     Aq0 + aoff, 16);
        size_t boff = (size_t)row * K + k0 + seg * 16;
        cp16(sb + 2 * TILE8 + so, Bq1 + boff, 16);
        cp16(sb + 3 * TILE8 + so, Bq0 + boff, 16);
    };

    issue(0, 0);
    CP_COMMIT();

    for (int c = 0; c < nk; ++c) {
        if (c + 1 < nk) {
            issue((c + 1) & 1, (c + 1) << 6);
            CP_COMMIT();
            cp_wait<1>();
        } else {
            cp_wait<0>();
        }
        __syncthreads();

        const uint32_t bA1 = sbase + (uint32_t)(c & 1) * STAGE8;
        const uint32_t bA0 = bA1 + TILE8;
        const uint32_t bB1 = bA1 + 2 * TILE8;
        const uint32_t bB0 = bA1 + 3 * TILE8;

        #pragma unroll
        for (int ks = 0; ks < 2; ++ks) {
            uint32_t aq1[2][4], aq0[2][4], bq1[2][4], bq0[2][4];
            #pragma unroll
            for (int i = 0; i < 2; ++i) {
                uint32_t ad = lds_addr(0, wm * 32 + i * 16, ks, lane);
                ldsm4(aq1[i], bA1 + ad);
                ldsm4(aq0[i], bA0 + ad);
            }
            #pragma unroll
            for (int j2 = 0; j2 < 2; ++j2) {
                uint32_t bd = lds_addr(0, wn * 32 + j2 * 16, ks, lane);
                ldsm4(bq1[j2], bB1 + bd);
                ldsm4(bq0[j2], bB0 + bd);
            }
            #pragma unroll
            for (int i = 0; i < 2; ++i)
                #pragma unroll
                for (int j2 = 0; j2 < 2; ++j2) {
                    mma_s8(d1[i][j2 * 2],     aq1[i], bq1[j2][0], bq1[j2][2]);
                    mma_s8(d1[i][j2 * 2 + 1], aq1[i], bq1[j2][1], bq1[j2][3]);
                    mma_s8(d2[i][j2 * 2],     aq1[i], bq0[j2][0], bq0[j2][2]);
                    mma_s8(d2[i][j2 * 2 + 1], aq1[i], bq0[j2][1], bq0[j2][3]);
                    mma_s8(d2[i][j2 * 2],     aq0[i], bq1[j2][0], bq1[j2][2]);
                    mma_s8(d2[i][j2 * 2 + 1], aq0[i], bq1[j2][1], bq1[j2][3]);
                }
        }
        __syncthreads();
    }

    // ---- epilogue: vector atomic scatter straight from registers ----
    const int q = lane >> 2;
    const int cpair = (lane & 3) * 2;
    #pragma unroll
    for (int i = 0; i < 2; ++i) {
        int le0 = wm * 32 + i * 16 + q;
        int gr0 = s_erow[le0];
        int gr1 = s_erow[le0 + 8];
        float sa0 = s_sa[le0];
        float sa1 = s_sa[le0 + 8];
        #pragma unroll
        for (int j = 0; j < 4; ++j) {
            int gc = wn * 32 + j * 8 + cpair;
            float sb0 = Bs[gc], sb1 = Bs[gc + 1];
            if (gr0 >= 0) {
                float* p = acc + (size_t)gr0 * DHID + gc;
                red_add2(p, sa0 * sb0 * recomb(d1[i][j][0], d2[i][j][0]),
                            sa0 * sb1 * recomb(d1[i][j][1], d2[i][j][1]));
            }
            if (gr1 >= 0) {
                float* p = acc + (size_t)gr1 * DHID + gc;
                red_add2(p, sa1 * sb0 * recomb(d1[i][j][2], d2[i][j][2]),
                            sa1 * sb1 * recomb(d1[i][j][3], d2[i][j][3]));
            }
        }
    }
}

// ---------------- edge sort (counting sort by relation) ----------------
__global__ void zero16() {
    if (threadIdx.x < NREL) g_cnt[threadIdx.x] = 0;
}
__global__ void hist_k(const int* __restrict__ et) {
    __shared__ int h[NREL];
    if (threadIdx.x < NREL) h[threadIdx.x] = 0;
    __syncthreads();
    int i = blockIdx.x * 256 + threadIdx.x;
    if (i < NEDGE) atomicAdd(&h[et[i]], 1);
    __syncthreads();
    if (threadIdx.x < NREL && h[threadIdx.x]) atomicAdd(&g_cnt[threadIdx.x], h[threadIdx.x]);
}
__global__ void prefix_k() {
    int o = 0, t = 0;
    for (int r = 0; r < NREL; ++r) {
        g_off[r] = o; g_cursor[r] = o; g_tilestart[r] = t;
        o += g_cnt[r]; t += (g_cnt[r] + 127) >> 7;
    }
    g_off[NREL] = o; g_tilestart[NREL] = t;
}
__global__ void scatter_k(const int* __restrict__ er, const int* __restrict__ ec,
                          const int* __restrict__ et) {
    __shared__ int h[NREL], base[NREL];
    if (threadIdx.x < NREL) h[threadIdx.x] = 0;
    __syncthreads();
    int i = blockIdx.x * 256 + threadIdx.x;
    int t = 0, my = 0;
    bool ok = i < NEDGE;
    if (ok) { t = et[i]; my = atomicAdd(&h[t], 1); }
    __syncthreads();
    if (threadIdx.x < NREL && h[threadIdx.x])
        base[threadIdx.x] = atomicAdd(&g_cursor[threadIdx.x], h[threadIdx.x]);
    __syncthreads();
    if (ok) {
        int p = base[t] + my;
        g_erow_s[p] = er[i];
        g_ecol_s[p] = ec[i];
    }
}

// ---------------- quantize entity embeddings (K=256, warp per row) ----------------
__global__ void quantE(const float* __restrict__ E,
                       int8_t* __restrict__ q1, int8_t* __restrict__ q0,
                       float* __restrict__ s) {
    int row = blockIdx.x * 8 + (threadIdx.x >> 5);
    if (row >= N_NODES) return;
    int lane = threadIdx.x & 31;
    const float* rp_ = E + (size_t)row * DEMB;
    float4 v0 = ((const float4*)rp_)[lane * 2];
    float4 v1 = ((const float4*)rp_)[lane * 2 + 1];
    float mx = fmaxf(fmaxf(fmaxf(fabsf(v0.x), fabsf(v0.y)), fmaxf(fabsf(v0.z), fabsf(v0.w))),
                     fmaxf(fmaxf(fabsf(v1.x), fabsf(v1.y)), fmaxf(fabsf(v1.z), fabsf(v1.w))));
    #pragma unroll
    for (int o = 16; o; o >>= 1) mx = fmaxf(mx, __shfl_xor_sync(0xFFFFFFFFu, mx, o));
    mx = fmaxf(mx, 1e-35f);
    float inv = 16256.f / mx;
    int h[8], l[8];
    quant1(v0.x, inv, h[0], l[0]); quant1(v0.y, inv, h[1], l[1]);
    quant1(v0.z, inv, h[2], l[2]); quant1(v0.w, inv, h[3], l[3]);
    quant1(v1.x, inv, h[4], l[4]); quant1(v1.y, inv, h[5], l[5]);
    quant1(v1.z, inv, h[6], l[6]); quant1(v1.w, inv, h[7], l[7]);
    uint32_t* p1 = (uint32_t*)(q1 + (size_t)row * DEMB);
    uint32_t* p0 = (uint32_t*)(q0 + (size_t)row * DEMB);
    p1[lane * 2]     = pack4i8(h[0], h[1], h[2], h[3]);
    p1[lane * 2 + 1] = pack4i8(h[4], h[5], h[6], h[7]);
    p0[lane * 2]     = pack4i8(l[0], l[1], l[2], l[3]);
    p0[lane * 2 + 1] = pack4i8(l[4], l[5], l[6], l[7]);
    if (lane == 0) s[row] = mx * (1.f / 16256.f);
}

// ---------------- quantized relation weights W_r^T: grid NREL*DHID, block din ----------------
__global__ void build_wrT_q(const float* __restrict__ bases,
                            const float* __restrict__ coeff,
                            int8_t* __restrict__ q1, int8_t* __restrict__ q0,
                            float* __restrict__ sc, int din) {
    __shared__ float red_[256];
    int bid = blockIdx.x;
    int r = bid >> 7;
    int n = bid & 127;
    int k = threadIdx.x;
    float v = 0.f;
    #pragma unroll
    for (int b = 0; b < NBAS; ++b)
        v += coeff[r * NBAS + b] * bases[((size_t)b * din + k) * DHID + n];
    red_[k] = fabsf(v);
    __syncthreads();
    for (int s = blockDim.x >> 1; s > 0; s >>= 1) {
        if (k < s) red_[k] = fmaxf(red_[k], red_[k + s]);
        __syncthreads();
    }
    float mx = fmaxf(red_[0], 1e-35f);
    float inv = 16256.f / mx;
    int h, l;
    quant1(v, inv, h, l);
    size_t o = (size_t)bid * din + k;
    q1[o] = (int8_t)h;
    q0[o] = (int8_t)l;
    if (k == 0) sc[bid] = mx * (1.f / 16256.f);
}

// ---------------- quantized selfw^T: grid DHID, block din ----------------
__global__ void build_selfT_q(const float* __restrict__ selfw,
                              int8_t* __restrict__ q1, int8_t* __restrict__ q0,
                              float* __restrict__ sc, int din) {
    __shared__ float red_[256];
    int n = blockIdx.x;
    int k = threadIdx.x;
    float v = selfw[(size_t)k * DHID + n];
    red_[k] = fabsf(v);
    __syncthreads();
    for (int s = blockDim.x >> 1; s > 0; s >>= 1) {
        if (k < s) red_[k] = fmaxf(red_[k], red_[k + s]);
        __syncthreads();
    }
    float mx = fmaxf(red_[0], 1e-35f);
    float inv = 16256.f / mx;
    int h, l;
    quant1(v, inv, h, l);
    size_t o = (size_t)n * din + k;
    q1[o] = (int8_t)h;
    q0[o] = (int8_t)l;
    if (k == 0) sc[n] = mx * (1.f / 16256.f);
}

// ---------------- quantized combined w1 head|tail transposed: grid 256, block 128 ----------------
__global__ void build_w1c_q(const float* __restrict__ w1,
                            int8_t* __restrict__ q1, int8_t* __restrict__ q0,
                            float* __restrict__ sc) {
    __shared__ float red_[128];
    int n = blockIdx.x;
    int k = threadIdx.x;
    float v = (n < DHID) ? w1[(size_t)k * DHID + n]
                         : w1[(size_t)(384 + k) * DHID + (n - DHID)];
    red_[k] = fabsf(v);
    __syncthreads();
    for (int s = 64; s > 0; s >>= 1) {
        if (k < s) red_[k] = fmaxf(red_[k], red_[k + s]);
        __syncthreads();
    }
    float mx = fmaxf(red_[0], 1e-35f);
    float inv = 16256.f / mx;
    int h, l;
    quant1(v, inv, h, l);
    size_t o = (size_t)n * DHID + k;
    q1[o] = (int8_t)h;
    q0[o] = (int8_t)l;
    if (k == 0) sc[n] = mx * (1.f / 16256.f);
}

// ---------------- relu + layernorm -> quantized int8 hi/lo ----------------
__global__ void relu_ln_q(const float* __restrict__ acc,
                          const float* __restrict__ gamma,
                          const float* __restrict__ beta,
                          int8_t* __restrict__ xq1, int8_t* __restrict__ xq0,
                          float* __restrict__ xs) {
    int n = blockIdx.x * 8 + (threadIdx.x >> 5);
    if (n >= N_NODES) return;
    int lane = threadIdx.x & 31;
    float4 v = ((const float4*)(acc + (size_t)n * DHID))[lane];
    v.x = fmaxf(v.x, 0.f); v.y = fmaxf(v.y, 0.f);
    v.z = fmaxf(v.z, 0.f); v.w = fmaxf(v.w, 0.f);
    float s = v.x + v.y + v.z + v.w;
    #pragma unroll
    for (int o = 16; o; o >>= 1) s += __shfl_xor_sync(0xFFFFFFFFu, s, o);
    float mu = s * (1.f / DHID);
    float dx = v.x - mu, dy = v.y - mu, dz = v.z - mu, dw = v.w - mu;
    float ss = dx * dx + dy * dy + dz * dz + dw * dw;
    #pragma unroll
    for (int o = 16; o; o >>= 1) ss += __shfl_xor_sync(0xFFFFFFFFu, ss, o);
    float invs = rsqrtf(ss * (1.f / DHID) + 1e-5f);
    float4 g = ((const float4*)gamma)[lane];
    float4 b = ((const float4*)beta)[lane];
    float ox = dx * invs * g.x + b.x;
    float oy = dy * invs * g.y + b.y;
    float oz = dz * invs * g.z + b.z;
    float ow = dw * invs * g.w + b.w;
    float mx = fmaxf(fmaxf(fabsf(ox), fabsf(oy)), fmaxf(fabsf(oz), fabsf(ow)));
    #pragma unroll
    for (int o = 16; o; o >>= 1) mx = fmaxf(mx, __shfl_xor_sync(0xFFFFFFFFu, mx, o));
    mx = fmaxf(mx, 1e-35f);
    float inv = 16256.f / mx;
    int h0, h1, h2, h3, l0, l1, l2, l3;
    quant1(ox, inv, h0, l0); quant1(oy, inv, h1, l1);
    quant1(oz, inv, h2, l2); quant1(ow, inv, h3, l3);
    ((uint32_t*)(xq1 + (size_t)n * DHID))[lane] = pack4i8(h0, h1, h2, h3);
    ((uint32_t*)(xq0 + (size_t)n * DHID))[lane] = pack4i8(l0, l1, l2, l3);
    if (lane == 0) xs[n] = mx * (1.f / 16256.f);
}

// ---------------- relproj: block per relation, coalesced w1 ----------------
__global__ void relproj_k(const float* __restrict__ relemb,
                          const float* __restrict__ w1,
                          const float* __restrict__ b1,
                          float* __restrict__ rp) {
    __shared__ float s_e[DEMB];
    int r = blockIdx.x;
    int j = threadIdx.x;
    for (int i = j; i < DEMB; i += DHID) s_e[i] = relemb[r * DEMB + i];
    __syncthreads();
    float s = b1[j];
    #pragma unroll 4
    for (int i = 0; i < DEMB; ++i)
        s = fmaf(s_e[i], w1[(size_t)(DHID + i) * DHID + j], s);
    rp[r * DHID + j] = s;
}

// ---------------- score ----------------
__global__ void score_k(const int* __restrict__ head,
                        const int* __restrict__ rel,
                        const int* __restrict__ tail,
                        const float* __restrict__ HPTP,
                        const float* __restrict__ rp,
                        const float* __restrict__ w2,
                        const float* __restrict__ b2,
                        float* __restrict__ out) {
    int q = blockIdx.x * 8 + (threadIdx.x >> 5);
    if (q >= NQUERY) return;
    int lane = threadIdx.x & 31;
    int h = head[q], r = rel[q], t = tail[q];
    float4 a = ((const float4*)(HPTP + (size_t)h * 256))[lane];
    float4 bb = ((const float4*)(HPTP + (size_t)t * 256 + DHID))[lane];
    float4 c = ((const float4*)(rp + (size_t)r * DHID))[lane];
    float4 w = ((const float4*)w2)[lane];
    float s = fmaxf(a.x + bb.x + c.x, 0.f) * w.x
            + fmaxf(a.y + bb.y + c.y, 0.f) * w.y
            + fmaxf(a.z + bb.z + c.z, 0.f) * w.z
            + fmaxf(a.w + bb.w + c.w, 0.f) * w.w;
    #pragma unroll
    for (int o = 16; o; o >>= 1) s += __shfl_xor_sync(0xFFFFFFFFu, s, o);
    if (lane == 0) out[q] = s + b2[0];
}

// ---------------- launch ----------------
extern "C" void kernel_launch(void* const* d_in, const int* in_sizes, int n_in,
                              void* d_out, int out_size) {
    (void)in_sizes; (void)n_in; (void)out_size;
    const int*   edge_index   = (const int*)d_in[0];
    const int*   edge_type    = (const int*)d_in[1];
    const int*   head_ids     = (const int*)d_in[2];
    const int*   relation_ids = (const int*)d_in[3];
    const int*   tail_ids     = (const int*)d_in[4];
    const float* entity_emb   = (const float*)d_in[5];
    const float* relation_emb = (const float*)d_in[6];
    const float* bases0       = (const float*)d_in[7];
    const float* coeff0       = (const float*)d_in[8];
    const float* selfw0       = (const float*)d_in[9];
    const float* bases1       = (const float*)d_in[10];
    const float* coeff1       = (const float*)d_in[11];
    const float* selfw1       = (const float*)d_in[12];
    const float* ln0_g        = (const float*)d_in[13];
    const float* ln0_b        = (const float*)d_in[14];
    const float* ln1_g        = (const float*)d_in[15];
    const float* ln1_b        = (const float*)d_in[16];
    const float* w1           = (const float*)d_in[17];
    const float* b1           = (const float*)d_in[18];
    const float* w2           = (const float*)d_in[19];
    const float* b2           = (const float*)d_in[20];
    float* out = (float*)d_out;

    int8_t *Eq1, *Eq0, *Wq1, *Wq0, *Sq1, *Sq0, *xq1, *xq0, *w1q1, *w1q0;
    float *Es, *Wsc, *Ssc, *xs, *w1sc, *acc, *HPTP, *rp;
    cudaGetSymbolAddress((void**)&Eq1, g_Eq1);
    cudaGetSymbolAddress((void**)&Eq0, g_Eq0);
    cudaGetSymbolAddress((void**)&Es,  g_Es);
    cudaGetSymbolAddress((void**)&Wq1, g_Wq1);
    cudaGetSymbolAddress((void**)&Wq0, g_Wq0);
    cudaGetSymbolAddress((void**)&Wsc, g_Wsc);
    cudaGetSymbolAddress((void**)&Sq1, g_Sq1);
    cudaGetSymbolAddress((void**)&Sq0, g_Sq0);
    cudaGetSymbolAddress((void**)&Ssc, g_Ssc);
    cudaGetSymbolAddress((void**)&xq1, g_xq1);
    cudaGetSymbolAddress((void**)&xq0, g_xq0);
    cudaGetSymbolAddress((void**)&xs,  g_xs);
    cudaGetSymbolAddress((void**)&w1q1, g_w1q1);
    cudaGetSymbolAddress((void**)&w1q0, g_w1q0);
    cudaGetSymbolAddress((void**)&w1sc, g_w1sc);
    cudaGetSymbolAddress((void**)&acc,  g_acc);
    cudaGetSymbolAddress((void**)&HPTP, g_HPTP);
    cudaGetSymbolAddress((void**)&rp,   g_rp);

    cudaFuncSetAttribute(gemm_s8,  cudaFuncAttributeMaxDynamicSharedMemorySize, SMEM8);
    cudaFuncSetAttribute(egemm_s8, cudaFuncAttributeMaxDynamicSharedMemorySize, SMEM8);

    const int* erow = edge_index;
    const int* ecol = edge_index + NEDGE;
    const int nM = (N_NODES + 127) / 128;   // 391

    // ----- edge sort by relation -----
    zero16<<<1, 32>>>();
    hist_k<<<(NEDGE + 255) / 256, 256>>>(edge_type);
    prefix_k<<<1, 1>>>();
    scatter_k<<<(NEDGE + 255) / 256, 256>>>(erow, ecol, edge_type);

    // ----- layer 0 -----
    quantE<<<(N_NODES + 7) / 8, 256>>>(entity_emb, Eq1, Eq0, Es);
    build_wrT_q<<<NREL * DHID, DEMB>>>(bases0, coeff0, Wq1, Wq0, Wsc, DEMB);
    build_selfT_q<<<DHID, DEMB>>>(selfw0, Sq1, Sq0, Ssc, DEMB);
    gemm_s8<<<dim3(1, nM), 512, SMEM8>>>(N_NODES, DEMB, Eq1, Eq0, Es, Sq1, Sq0, Ssc, acc, DHID);
    egemm_s8<<<EGRID, 512, SMEM8>>>(DEMB, Eq1, Eq0, Es, Wq1, Wq0, Wsc, acc);
    relu_ln_q<<<(N_NODES + 7) / 8, 256>>>(acc, ln0_g, ln0_b, xq1, xq0, xs);

    // ----- layer 1 -----
    build_wrT_q<<<NREL * DHID, DHID>>>(bases1, coeff1, Wq1, Wq0, Wsc, DHID);
    build_selfT_q<<<DHID, DHID>>>(selfw1, Sq1, Sq0, Ssc, DHID);
    gemm_s8<<<dim3(1, nM), 512, SMEM8>>>(N_NODES, DHID, xq1, xq0, xs, Sq1, Sq0, Ssc, acc, DHID);
    egemm_s8<<<EGRID, 512, SMEM8>>>(DHID, xq1, xq0, xs, Wq1, Wq0, Wsc, acc);
    relu_ln_q<<<(N_NODES + 7) / 8, 256>>>(acc, ln1_g, ln1_b, xq1, xq0, xs);

    // ----- scoring -----
    relproj_k<<<NREL, DHID>>>(relation_emb, w1, b1, rp);
    build_w1c_q<<<2 * DHID, DHID>>>(w1, w1q1, w1q0, w1sc);
    gemm_s8<<<dim3(2, nM), 512, SMEM8>>>(N_NODES, DHID, xq1, xq0, xs, w1q1, w1q0, w1sc, HPTP, 256);
    score_k<<<(NQUERY + 7) / 8, 256>>>(head_ids, relation_ids, tail_ids, HPTP, rp, w2, b2, out);
}

// round 10
// speedup vs baseline: 1.1679x; 1.0082x over previous
#include <cuda_runtime.h>
#include <cuda_bf16.h>
#include <cstdint>

#define N_NODES 50000
#define NREL    16
#define NBAS    16
#define DEMB    256
#define DHID    128
#define NEDGE   300000
#define NQUERY  100000
#define EGRID   ((NEDGE + 127) / 128 + 16)

// ---------------- scratch (static __device__ globals; no allocation) ----------------
__device__ int8_t g_Eq1[(size_t)N_NODES * DEMB];
__device__ int8_t g_Eq0[(size_t)N_NODES * DEMB];
__device__ float  g_Es[N_NODES];
__device__ int8_t g_Wq1[(size_t)NREL * DHID * DEMB];
__device__ int8_t g_Wq0[(size_t)NREL * DHID * DEMB];
__device__ float  g_Wsc[NREL * DHID];
__device__ int8_t g_Sq1[DHID * DEMB];
__device__ int8_t g_Sq0[DHID * DEMB];
__device__ float  g_Ssc[DHID];
__device__ int8_t g_xq1[N_NODES * DHID];
__device__ int8_t g_xq0[N_NODES * DHID];
__device__ float  g_xs[N_NODES];
__device__ int8_t g_w1q1[2 * DHID * DHID];
__device__ int8_t g_w1q0[2 * DHID * DHID];
__device__ float  g_w1sc[2 * DHID];
__device__ float g_acc[N_NODES * DHID];
__device__ float g_HPTP[(size_t)N_NODES * 2 * DHID];
__device__ float g_rp[NREL * DHID];
// edge sort
__device__ int g_cnt[NREL];
__device__ int g_off[NREL + 1];
__device__ int g_tilestart[NREL + 1];
__device__ int g_cursor[NREL];
__device__ int g_erow_s[NEDGE];
__device__ int g_ecol_s[NEDGE];

__device__ __forceinline__ uint32_t smem_u32(const void* p) {
    uint32_t a;
    asm("{ .reg .u64 t; cvta.to.shared.u64 t, %1; cvt.u32.u64 %0, t; }" : "=r"(a) : "l"(p));
    return a;
}
__device__ __forceinline__ void ldsm4(uint32_t* r, uint32_t addr) {
    asm volatile("ldmatrix.sync.aligned.m8n8.x4.shared.b16 {%0,%1,%2,%3}, [%4];"
                 : "=r"(r[0]), "=r"(r[1]), "=r"(r[2]), "=r"(r[3]) : "r"(addr));
}
__device__ __forceinline__ void mma_s8(int* d, const uint32_t* a, uint32_t b0, uint32_t b1) {
    asm volatile(
        "mma.sync.aligned.m16n8k32.row.col.s32.s8.s8.s32 "
        "{%0,%1,%2,%3}, {%4,%5,%6,%7}, {%8,%9}, {%0,%1,%2,%3};"
        : "+r"(d[0]), "+r"(d[1]), "+r"(d[2]), "+r"(d[3])
        : "r"(a[0]), "r"(a[1]), "r"(a[2]), "r"(a[3]), "r"(b0), "r"(b1));
}
__device__ __forceinline__ void cp16(uint32_t dst, const void* src, int srcBytes) {
    asm volatile("cp.async.cg.shared.global [%0], [%1], 16, %2;"
                 :: "r"(dst), "l"(src), "r"(srcBytes));
}
#define CP_COMMIT() asm volatile("cp.async.commit_group;" ::: "memory")
template<int Nw> __device__ __forceinline__ void cp_wait() {
    asm volatile("cp.async.wait_group %0;" :: "n"(Nw) : "memory");
}
__device__ __forceinline__ void red_add2(float* p, float a, float b) {
    asm volatile("red.global.add.v2.f32 [%0], {%1,%2};"
                 :: "l"(p), "f"(a), "f"(b) : "memory");
}
__device__ __forceinline__ uint32_t pack4i8(int a, int b, int c, int d) {
    return (uint32_t)(a & 0xff) | ((uint32_t)(b & 0xff) << 8) |
           ((uint32_t)(c & 0xff) << 16) | ((uint32_t)(d & 0xff) << 24);
}
__device__ __forceinline__ void quant1(float v, float inv, int& h, int& l) {
    float q = v * inv;                       // |q| <= 16256
    h = __float2int_rn(q * (1.f / 128.f));
    l = __float2int_rn(q - 128.f * (float)h);
}
__device__ __forceinline__ float recomb(int d1, int d2) {
    return fmaf(128.f, (float)d2, 16384.f * (float)d1);
}

#define TILE8  8192                   // 128 rows x 64 bytes
#define STAGE8 (4 * TILE8)            // 32 KB
#define SMEM8  (2 * STAGE8)           // 64 KB

// smem addressing: 64B rows, 4x16B segs, swizzle seg ^= (row>>1)&3
__device__ __forceinline__ uint32_t sw_off(int row, int seg) {
    return (uint32_t)(row * 64) + ((uint32_t)(seg ^ ((row >> 1) & 3)) << 4);
}
__device__ __forceinline__ uint32_t lds_addr(uint32_t tb, int row0, int ks, int lane) {
    int row = row0 + (lane & 7) + ((lane >> 3) & 1) * 8;
    int seg = ks * 2 + (lane >> 4);
    return tb + sw_off(row, seg);
}

// ============================================================================
// Dense int8 GEMM: C[M,N] = (Aq,As) @ (Bq,Bs)^T ; grid (N/128, ceil(M/128)), 512 thr
// ============================================================================
__global__ __launch_bounds__(512, 1)
void gemm_s8(int M, int K,
             const int8_t* __restrict__ Aq1, const int8_t* __restrict__ Aq0,
             const float* __restrict__ As,
             const int8_t* __restrict__ Bq1, const int8_t* __restrict__ Bq0,
             const float* __restrict__ Bs,
             float* __restrict__ C, int ldc)
{
    extern __shared__ char sm[];
    const uint32_t sbase = smem_u32(sm);
    const int tid  = threadIdx.x;
    const int wid  = tid >> 5;
    const int lane = tid & 31;
    const int wm   = wid & 3;
    const int wn   = wid >> 2;
    const int mBase = blockIdx.y * 128;
    const int nBase = blockIdx.x * 128;

    int d1[2][4][4], d2[2][4][4];
    #pragma unroll
    for (int i = 0; i < 2; ++i)
        #pragma unroll
        for (int j = 0; j < 4; ++j)
            #pragma unroll
            for (int t = 0; t < 4; ++t) { d1[i][j][t] = 0; d2[i][j][t] = 0; }

    const int nk = K >> 6;

    auto issue = [&](int s, int k0) {
        const uint32_t sb = sbase + (uint32_t)s * STAGE8;
        int row = tid >> 2;
        int seg = tid & 3;
        uint32_t so = sw_off(row, seg);
        int gr = mBase + row;
        int okA = (gr < M) ? 16 : 0;
        size_t aoff = (size_t)(okA ? gr : 0) * K + k0 + seg * 16;
        cp16(sb + so,             Aq1 + aoff, okA);
        cp16(sb + TILE8 + so,     Aq0 + aoff, okA);
        size_t boff = (size_t)(nBase + row) * K + k0 + seg * 16;
        cp16(sb + 2 * TILE8 + so, Bq1 + boff, 16);
        cp16(sb + 3 * TILE8 + so, Bq0 + boff, 16);
    };

    issue(0, 0);
    CP_COMMIT();

    for (int c = 0; c < nk; ++c) {
        if (c + 1 < nk) {
            issue((c + 1) & 1, (c + 1) << 6);
            CP_COMMIT();
            cp_wait<1>();
        } else {
            cp_wait<0>();
        }
        __syncthreads();

        const uint32_t bA1 = sbase + (uint32_t)(c & 1) * STAGE8;
        const uint32_t bA0 = bA1 + TILE8;
        const uint32_t bB1 = bA1 + 2 * TILE8;
        const uint32_t bB0 = bA1 + 3 * TILE8;

        #pragma unroll
        for (int ks = 0; ks < 2; ++ks) {
            uint32_t aq1[2][4], aq0[2][4], bq1[2][4], bq0[2][4];
            #pragma unroll
            for (int i = 0; i < 2; ++i) {
                uint32_t ad = lds_addr(0, wm * 32 + i * 16, ks, lane);
                ldsm4(aq1[i], bA1 + ad);
                ldsm4(aq0[i], bA0 + ad);
            }
            #pragma unroll
            for (int j2 = 0; j2 < 2; ++j2) {
                uint32_t bd = lds_addr(0, wn * 32 + j2 * 16, ks, lane);
                ldsm4(bq1[j2], bB1 + bd);
                ldsm4(bq0[j2], bB0 + bd);
            }
            #pragma unroll
            for (int i = 0; i < 2; ++i)
                #pragma unroll
                for (int j2 = 0; j2 < 2; ++j2) {
                    mma_s8(d1[i][j2 * 2],     aq1[i], bq1[j2][0], bq1[j2][2]);
                    mma_s8(d1[i][j2 * 2 + 1], aq1[i], bq1[j2][1], bq1[j2][3]);
                    mma_s8(d2[i][j2 * 2],     aq1[i], bq0[j2][0], bq0[j2][2]);
                    mma_s8(d2[i][j2 * 2 + 1], aq1[i], bq0[j2][1], bq0[j2][3]);
                    mma_s8(d2[i][j2 * 2],     aq0[i], bq1[j2][0], bq1[j2][2]);
                    mma_s8(d2[i][j2 * 2 + 1], aq0[i], bq1[j2][1], bq1[j2][3]);
                }
        }
        __syncthreads();
    }

    const int q = lane >> 2;
    const int cpair = (lane & 3) * 2;
    #pragma unroll
    for (int i = 0; i < 2; ++i) {
        int gr0 = mBase + wm * 32 + i * 16 + q;
        float sa0 = (gr0 < M) ? As[gr0] : 0.f;
        float sa1 = (gr0 + 8 < M) ? As[gr0 + 8] : 0.f;
        #pragma unroll
        for (int j = 0; j < 4; ++j) {
            int gc = nBase + wn * 32 + j * 8 + cpair;
            float sb0 = Bs[gc], sb1 = Bs[gc + 1];
            if (gr0 < M) {
                float v0 = sa0 * sb0 * recomb(d1[i][j][0], d2[i][j][0]);
                float v1 = sa0 * sb1 * recomb(d1[i][j][1], d2[i][j][1]);
                *(float2*)(C + (size_t)gr0 * ldc + gc) = make_float2(v0, v1);
            }
            if (gr0 + 8 < M) {
                float v2 = sa1 * sb0 * recomb(d1[i][j][2], d2[i][j][2]);
                float v3 = sa1 * sb1 * recomb(d1[i][j][3], d2[i][j][3]);
                *(float2*)(C + (size_t)(gr0 + 8) * ldc + gc) = make_float2(v2, v3);
            }
        }
    }
}

// ============================================================================
// Edge int8 GEMM: acc[row[e], :] += x[col[e], :] @ W_r^T
// Epilogue: red.global.add.v2.f32 straight from accumulator registers
// ============================================================================
__global__ __launch_bounds__(512, 1)
void egemm_s8(int K,
              const int8_t* __restrict__ Aq1, const int8_t* __restrict__ Aq0,
              const float* __restrict__ As,
              const int8_t* __restrict__ Wq1, const int8_t* __restrict__ Wq0,
              const float* __restrict__ Wsc,
              float* __restrict__ acc)
{
    extern __shared__ char sm[];
    __shared__ int s_ecol[128];
    __shared__ int s_erow[128];
    __shared__ float s_sa[128];
    const uint32_t sbase = smem_u32(sm);

    const int bid = blockIdx.x;
    if (bid >= g_tilestart[NREL]) return;
    int r = 0;
    #pragma unroll
    for (int i = 0; i < NREL - 1; ++i)
        if (bid >= g_tilestart[i + 1]) r = i + 1;
    const int tile = bid - g_tilestart[r];
    const int estart = g_off[r] + tile * 128;
    const int medge = min(128, g_off[r + 1] - estart);

    const int tid  = threadIdx.x;
    const int wid  = tid >> 5;
    const int lane = tid & 31;
    const int wm   = wid & 3;
    const int wn   = wid >> 2;

    if (tid < 128) {
        bool ok = tid < medge;
        int c = ok ? g_ecol_s[estart + tid] : 0;
        s_ecol[tid] = c;
        s_erow[tid] = ok ? g_erow_s[estart + tid] : -1;
        s_sa[tid] = As[c];
    }
    __syncthreads();

    const int8_t* Bq1 = Wq1 + (size_t)r * DHID * K;
    const int8_t* Bq0 = Wq0 + (size_t)r * DHID * K;
    const float*  Bs  = Wsc + r * DHID;

    int d1[2][4][4], d2[2][4][4];
    #pragma unroll
    for (int i = 0; i < 2; ++i)
        #pragma unroll
        for (int j = 0; j < 4; ++j)
            #pragma unroll
            for (int t = 0; t < 4; ++t) { d1[i][j][t] = 0; d2[i][j][t] = 0; }

    const int nk = K >> 6;

    auto issue = [&](int s, int k0) {
        const uint32_t sb = sbase + (uint32_t)s * STAGE8;
        int row = tid >> 2;
        int seg = tid & 3;
        uint32_t so = sw_off(row, seg);
        size_t aoff = (size_t)s_ecol[row] * K + k0 + seg * 16;
        cp16(sb + so,             Aq1 + aoff, 16);
        cp16(sb + TILE8 + so,     Aq0 + aoff, 16);
        size_t boff = (size_t)row * K + k0 + seg * 16;
        cp16(sb + 2 * TILE8 + so, Bq1 + boff, 16);
        cp16(sb + 3 * TILE8 + so, Bq0 + boff, 16);
    };

    issue(0, 0);
    CP_COMMIT();

    for (int c = 0; c < nk; ++c) {
        if (c + 1 < nk) {
            issue((c + 1) & 1, (c + 1) << 6);
            CP_COMMIT();
            cp_wait<1>();
        } else {
            cp_wait<0>();
        }
        __syncthreads();

        const uint32_t bA1 = sbase + (uint32_t)(c & 1) * STAGE8;
        const uint32_t bA0 = bA1 + TILE8;
        const uint32_t bB1 = bA1 + 2 * TILE8;
        const uint32_t bB0 = bA1 + 3 * TILE8;

        #pragma unroll
        for (int ks = 0; ks < 2; ++ks) {
            uint32_t aq1[2][4], aq0[2][4], bq1[2][4], bq0[2][4];
            #pragma unroll
            for (int i = 0; i < 2; ++i) {
                uint32_t ad = lds_addr(0, wm * 32 + i * 16, ks, lane);
                ldsm4(aq1[i], bA1 + ad);
                ldsm4(aq0[i], bA0 + ad);
            }
            #pragma unroll
            for (int j2 = 0; j2 < 2; ++j2) {
                uint32_t bd = lds_addr(0, wn * 32 + j2 * 16, ks, lane);
                ldsm4(bq1[j2], bB1 + bd);
                ldsm4(bq0[j2], bB0 + bd);
            }
            #pragma unroll
            for (int i = 0; i < 2; ++i)
                #pragma unroll
                for (int j2 = 0; j2 < 2; ++j2) {
                    mma_s8(d1[i][j2 * 2],     aq1[i], bq1[j2][0], bq1[j2][2]);
                    mma_s8(d1[i][j2 * 2 + 1], aq1[i], bq1[j2][1], bq1[j2][3]);
                    mma_s8(d2[i][j2 * 2],     aq1[i], bq0[j2][0], bq0[j2][2]);
                    mma_s8(d2[i][j2 * 2 + 1], aq1[i], bq0[j2][1], bq0[j2][3]);
                    mma_s8(d2[i][j2 * 2],     aq0[i], bq1[j2][0], bq1[j2][2]);
                    mma_s8(d2[i][j2 * 2 + 1], aq0[i], bq1[j2][1], bq1[j2][3]);
                }
        }
        __syncthreads();
    }

    // ---- epilogue: vector atomic scatter straight from registers ----
    const int q = lane >> 2;
    const int cpair = (lane & 3) * 2;
    #pragma unroll
    for (int i = 0; i < 2; ++i) {
        int le0 = wm * 32 + i * 16 + q;
        int gr0 = s_erow[le0];
        int gr1 = s_erow[le0 + 8];
        float sa0 = s_sa[le0];
        float sa1 = s_sa[le0 + 8];
        #pragma unroll
        for (int j = 0; j < 4; ++j) {
            int gc = wn * 32 + j * 8 + cpair;
            float sb0 = Bs[gc], sb1 = Bs[gc + 1];
            if (gr0 >= 0) {
                float* p = acc + (size_t)gr0 * DHID + gc;
                red_add2(p, sa0 * sb0 * recomb(d1[i][j][0], d2[i][j][0]),
                            sa0 * sb1 * recomb(d1[i][j][1], d2[i][j][1]));
            }
            if (gr1 >= 0) {
                float* p = acc + (size_t)gr1 * DHID + gc;
                red_add2(p, sa1 * sb0 * recomb(d1[i][j][2], d2[i][j][2]),
                            sa1 * sb1 * recomb(d1[i][j][3], d2[i][j][3]));
            }
        }
    }
}

// ---------------- edge sort (counting sort by relation) ----------------
__global__ void zero16() {
    if (threadIdx.x < NREL) g_cnt[threadIdx.x] = 0;
}
__global__ void hist_k(const int* __restrict__ et) {
    __shared__ int h[NREL];
    if (threadIdx.x < NREL) h[threadIdx.x] = 0;
    __syncthreads();
    int i = blockIdx.x * 256 + threadIdx.x;
    if (i < NEDGE) atomicAdd(&h[et[i]], 1);
    __syncthreads();
    if (threadIdx.x < NREL && h[threadIdx.x]) atomicAdd(&g_cnt[threadIdx.x], h[threadIdx.x]);
}
__global__ void prefix_k() {
    int o = 0, t = 0;
    for (int r = 0; r < NREL; ++r) {
        g_off[r] = o; g_cursor[r] = o; g_tilestart[r] = t;
        o += g_cnt[r]; t += (g_cnt[r] + 127) >> 7;
    }
    g_off[NREL] = o; g_tilestart[NREL] = t;
}
__global__ void scatter_k(const int* __restrict__ er, const int* __restrict__ ec,
                          const int* __restrict__ et) {
    __shared__ int h[NREL], base[NREL];
    if (threadIdx.x < NREL) h[threadIdx.x] = 0;
    __syncthreads();
    int i = blockIdx.x * 256 + threadIdx.x;
    int t = 0, my = 0;
    bool ok = i < NEDGE;
    if (ok) { t = et[i]; my = atomicAdd(&h[t], 1); }
    __syncthreads();
    if (threadIdx.x < NREL && h[threadIdx.x])
        base[threadIdx.x] = atomicAdd(&g_cursor[threadIdx.x], h[threadIdx.x]);
    __syncthreads();
    if (ok) {
        int p = base[t] + my;
        g_erow_s[p] = er[i];
        g_ecol_s[p] = ec[i];
    }
}

// ---------------- quantize entity embeddings (K=256, warp per row) ----------------
__global__ void quantE(const float* __restrict__ E,
                       int8_t* __restrict__ q1, int8_t* __restrict__ q0,
                       float* __restrict__ s) {
    int row = blockIdx.x * 8 + (threadIdx.x >> 5);
    if (row >= N_NODES) return;
    int lane = threadIdx.x & 31;
    const float* rp_ = E + (size_t)row * DEMB;
    float4 v0 = ((const float4*)rp_)[lane * 2];
    float4 v1 = ((const float4*)rp_)[lane * 2 + 1];
    float mx = fmaxf(fmaxf(fmaxf(fabsf(v0.x), fabsf(v0.y)), fmaxf(fabsf(v0.z), fabsf(v0.w))),
                     fmaxf(fmaxf(fabsf(v1.x), fabsf(v1.y)), fmaxf(fabsf(v1.z), fabsf(v1.w))));
    #pragma unroll
    for (int o = 16; o; o >>= 1) mx = fmaxf(mx, __shfl_xor_sync(0xFFFFFFFFu, mx, o));
    mx = fmaxf(mx, 1e-35f);
    float inv = 16256.f / mx;
    int h[8], l[8];
    quant1(v0.x, inv, h[0], l[0]); quant1(v0.y, inv, h[1], l[1]);
    quant1(v0.z, inv, h[2], l[2]); quant1(v0.w, inv, h[3], l[3]);
    quant1(v1.x, inv, h[4], l[4]); quant1(v1.y, inv, h[5], l[5]);
    quant1(v1.z, inv, h[6], l[6]); quant1(v1.w, inv, h[7], l[7]);
    uint32_t* p1 = (uint32_t*)(q1 + (size_t)row * DEMB);
    uint32_t* p0 = (uint32_t*)(q0 + (size_t)row * DEMB);
    p1[lane * 2]     = pack4i8(h[0], h[1], h[2], h[3]);
    p1[lane * 2 + 1] = pack4i8(h[4], h[5], h[6], h[7]);
    p0[lane * 2]     = pack4i8(l[0], l[1], l[2], l[3]);
    p0[lane * 2 + 1] = pack4i8(l[4], l[5], l[6], l[7]);
    if (lane == 0) s[row] = mx * (1.f / 16256.f);
}

// ---------------- quantized relation weights W_r^T: grid NREL*DHID, block din ----------------
__global__ void build_wrT_q(const float* __restrict__ bases,
                            const float* __restrict__ coeff,
                            int8_t* __restrict__ q1, int8_t* __restrict__ q0,
                            float* __restrict__ sc, int din) {
    __shared__ float red_[256];
    int bid = blockIdx.x;
    int r = bid >> 7;
    int n = bid & 127;
    int k = threadIdx.x;
    float v = 0.f;
    #pragma unroll
    for (int b = 0; b < NBAS; ++b)
        v += coeff[r * NBAS + b] * bases[((size_t)b * din + k) * DHID + n];
    red_[k] = fabsf(v);
    __syncthreads();
    for (int s = blockDim.x >> 1; s > 0; s >>= 1) {
        if (k < s) red_[k] = fmaxf(red_[k], red_[k + s]);
        __syncthreads();
    }
    float mx = fmaxf(red_[0], 1e-35f);
    float inv = 16256.f / mx;
    int h, l;
    quant1(v, inv, h, l);
    size_t o = (size_t)bid * din + k;
    q1[o] = (int8_t)h;
    q0[o] = (int8_t)l;
    if (k == 0) sc[bid] = mx * (1.f / 16256.f);
}

// ---------------- quantized selfw^T: grid DHID, block din ----------------
__global__ void build_selfT_q(const float* __restrict__ selfw,
                              int8_t* __restrict__ q1, int8_t* __restrict__ q0,
                              float* __restrict__ sc, int din) {
    __shared__ float red_[256];
    int n = blockIdx.x;
    int k = threadIdx.x;
    float v = selfw[(size_t)k * DHID + n];
    red_[k] = fabsf(v);
    __syncthreads();
    for (int s = blockDim.x >> 1; s > 0; s >>= 1) {
        if (k < s) red_[k] = fmaxf(red_[k], red_[k + s]);
        __syncthreads();
    }
    float mx = fmaxf(red_[0], 1e-35f);
    float inv = 16256.f / mx;
    int h, l;
    quant1(v, inv, h, l);
    size_t o = (size_t)n * din + k;
    q1[o] = (int8_t)h;
    q0[o] = (int8_t)l;
    if (k == 0) sc[n] = mx * (1.f / 16256.f);
}

// ---------------- quantized combined w1 head|tail transposed: grid 256, block 128 ----------------
__global__ void build_w1c_q(const float* __restrict__ w1,
                            int8_t* __restrict__ q1, int8_t* __restrict__ q0,
                            float* __restrict__ sc) {
    __shared__ float red_[128];
    int n = blockIdx.x;
    int k = threadIdx.x;
    float v = (n < DHID) ? w1[(size_t)k * DHID + n]
                         : w1[(size_t)(384 + k) * DHID + (n - DHID)];
    red_[k] = fabsf(v);
    __syncthreads();
    for (int s = 64; s > 0; s >>= 1) {
        if (k < s) red_[k] = fmaxf(red_[k], red_[k + s]);
        __syncthreads();
    }
    float mx = fmaxf(red_[0], 1e-35f);
    float inv = 16256.f / mx;
    int h, l;
    quant1(v, inv, h, l);
    size_t o = (size_t)n * DHID + k;
    q1[o] = (int8_t)h;
    q0[o] = (int8_t)l;
    if (k == 0) sc[n] = mx * (1.f / 16256.f);
}

// ---------------- relu + layernorm -> quantized int8 hi/lo ----------------
__global__ void relu_ln_q(const float* __restrict__ acc,
                          const float* __restrict__ gamma,
                          const float* __restrict__ beta,
                          int8_t* __restrict__ xq1, int8_t* __restrict__ xq0,
                          float* __restrict__ xs) {
    int n = blockIdx.x * 8 + (threadIdx.x >> 5);
    if (n >= N_NODES) return;
    int lane = threadIdx.x & 31;
    float4 v = ((const float4*)(acc + (size_t)n * DHID))[lane];
    v.x = fmaxf(v.x, 0.f); v.y = fmaxf(v.y, 0.f);
    v.z = fmaxf(v.z, 0.f); v.w = fmaxf(v.w, 0.f);
    float s = v.x + v.y + v.z + v.w;
    #pragma unroll
    for (int o = 16; o; o >>= 1) s += __shfl_xor_sync(0xFFFFFFFFu, s, o);
    float mu = s * (1.f / DHID);
    float dx = v.x - mu, dy = v.y - mu, dz = v.z - mu, dw = v.w - mu;
    float ss = dx * dx + dy * dy + dz * dz + dw * dw;
    #pragma unroll
    for (int o = 16; o; o >>= 1) ss += __shfl_xor_sync(0xFFFFFFFFu, ss, o);
    float invs = rsqrtf(ss * (1.f / DHID) + 1e-5f);
    float4 g = ((const float4*)gamma)[lane];
    float4 b = ((const float4*)beta)[lane];
    float ox = dx * invs * g.x + b.x;
    float oy = dy * invs * g.y + b.y;
    float oz = dz * invs * g.z + b.z;
    float ow = dw * invs * g.w + b.w;
    float mx = fmaxf(fmaxf(fabsf(ox), fabsf(oy)), fmaxf(fabsf(oz), fabsf(ow)));
    #pragma unroll
    for (int o = 16; o; o >>= 1) mx = fmaxf(mx, __shfl_xor_sync(0xFFFFFFFFu, mx, o));
    mx = fmaxf(mx, 1e-35f);
    float inv = 16256.f / mx;
    int h0, h1, h2, h3, l0, l1, l2, l3;
    quant1(ox, inv, h0, l0); quant1(oy, inv, h1, l1);
    quant1(oz, inv, h2, l2); quant1(ow, inv, h3, l3);
    ((uint32_t*)(xq1 + (size_t)n * DHID))[lane] = pack4i8(h0, h1, h2, h3);
    ((uint32_t*)(xq0 + (size_t)n * DHID))[lane] = pack4i8(l0, l1, l2, l3);
    if (lane == 0) xs[n] = mx * (1.f / 16256.f);
}

// ---------------- relproj: block per relation, coalesced w1 ----------------
__global__ void relproj_k(const float* __restrict__ relemb,
                          const float* __restrict__ w1,
                          const float* __restrict__ b1,
                          float* __restrict__ rp) {
    __shared__ float s_e[DEMB];
    int r = blockIdx.x;
    int j = threadIdx.x;
    for (int i = j; i < DEMB; i += DHID) s_e[i] = relemb[r * DEMB + i];
    __syncthreads();
    float s = b1[j];
    #pragma unroll 4
    for (int i = 0; i < DEMB; ++i)
        s = fmaf(s_e[i], w1[(size_t)(DHID + i) * DHID + j], s);
    rp[r * DHID + j] = s;
}

// ---------------- score ----------------
__global__ void score_k(const int* __restrict__ head,
                        const int* __restrict__ rel,
                        const int* __restrict__ tail,
                        const float* __restrict__ HPTP,
                        const float* __restrict__ rp,
                        const float* __restrict__ w2,
                        const float* __restrict__ b2,
                        float* __restrict__ out) {
    int q = blockIdx.x * 8 + (threadIdx.x >> 5);
    if (q >= NQUERY) return;
    int lane = threadIdx.x & 31;
    int h = head[q], r = rel[q], t = tail[q];
    float4 a = ((const float4*)(HPTP + (size_t)h * 256))[lane];
    float4 bb = ((const float4*)(HPTP + (size_t)t * 256 + DHID))[lane];
    float4 c = ((const float4*)(rp + (size_t)r * DHID))[lane];
    float4 w = ((const float4*)w2)[lane];
    float s = fmaxf(a.x + bb.x + c.x, 0.f) * w.x
            + fmaxf(a.y + bb.y + c.y, 0.f) * w.y
            + fmaxf(a.z + bb.z + c.z, 0.f) * w.z
            + fmaxf(a.w + bb.w + c.w, 0.f) * w.w;
    #pragma unroll
    for (int o = 16; o; o >>= 1) s += __shfl_xor_sync(0xFFFFFFFFu, s, o);
    if (lane == 0) out[q] = s + b2[0];
}

// ---------------- launch ----------------
extern "C" void kernel_launch(void* const* d_in, const int* in_sizes, int n_in,
                              void* d_out, int out_size) {
    (void)in_sizes; (void)n_in; (void)out_size;
    const int*   edge_index   = (const int*)d_in[0];
    const int*   edge_type    = (const int*)d_in[1];
    const int*   head_ids     = (const int*)d_in[2];
    const int*   relation_ids = (const int*)d_in[3];
    const int*   tail_ids     = (const int*)d_in[4];
    const float* entity_emb   = (const float*)d_in[5];
    const float* relation_emb = (const float*)d_in[6];
    const float* bases0       = (const float*)d_in[7];
    const float* coeff0       = (const float*)d_in[8];
    const float* selfw0       = (const float*)d_in[9];
    const float* bases1       = (const float*)d_in[10];
    const float* coeff1       = (const float*)d_in[11];
    const float* selfw1       = (const float*)d_in[12];
    const float* ln0_g        = (const float*)d_in[13];
    const float* ln0_b        = (const float*)d_in[14];
    const float* ln1_g        = (const float*)d_in[15];
    const float* ln1_b        = (const float*)d_in[16];
    const float* w1           = (const float*)d_in[17];
    const float* b1           = (const float*)d_in[18];
    const float* w2           = (const float*)d_in[19];
    const float* b2           = (const float*)d_in[20];
    float* out = (float*)d_out;

    int8_t *Eq1, *Eq0, *Wq1, *Wq0, *Sq1, *Sq0, *xq1, *xq0, *w1q1, *w1q0;
    float *Es, *Wsc, *Ssc, *xs, *w1sc, *acc, *HPTP, *rp;
    cudaGetSymbolAddress((void**)&Eq1, g_Eq1);
    cudaGetSymbolAddress((void**)&Eq0, g_Eq0);
    cudaGetSymbolAddress((void**)&Es,  g_Es);
    cudaGetSymbolAddress((void**)&Wq1, g_Wq1);
    cudaGetSymbolAddress((void**)&Wq0, g_Wq0);
    cudaGetSymbolAddress((void**)&Wsc, g_Wsc);
    cudaGetSymbolAddress((void**)&Sq1, g_Sq1);
    cudaGetSymbolAddress((void**)&Sq0, g_Sq0);
    cudaGetSymbolAddress((void**)&Ssc, g_Ssc);
    cudaGetSymbolAddress((void**)&xq1, g_xq1);
    cudaGetSymbolAddress((void**)&xq0, g_xq0);
    cudaGetSymbolAddress((void**)&xs,  g_xs);
    cudaGetSymbolAddress((void**)&w1q1, g_w1q1);
    cudaGetSymbolAddress((void**)&w1q0, g_w1q0);
    cudaGetSymbolAddress((void**)&w1sc, g_w1sc);
    cudaGetSymbolAddress((void**)&acc,  g_acc);
    cudaGetSymbolAddress((void**)&HPTP, g_HPTP);
    cudaGetSymbolAddress((void**)&rp,   g_rp);

    cudaFuncSetAttribute(gemm_s8,  cudaFuncAttributeMaxDynamicSharedMemorySize, SMEM8);
    cudaFuncSetAttribute(egemm_s8, cudaFuncAttributeMaxDynamicSharedMemorySize, SMEM8);

    const int* erow = edge_index;
    const int* ecol = edge_index + NEDGE;
    const int nM = (N_NODES + 127) / 128;   // 391

    // ----- edge sort by relation -----
    zero16<<<1, 32>>>();
    hist_k<<<(NEDGE + 255) / 256, 256>>>(edge_type);
    prefix_k<<<1, 1>>>();
    scatter_k<<<(NEDGE + 255) / 256, 256>>>(erow, ecol, edge_type);

    // ----- layer 0 -----
    quantE<<<(N_NODES + 7) / 8, 256>>>(entity_emb, Eq1, Eq0, Es);
    build_wrT_q<<<NREL * DHID, DEMB>>>(bases0, coeff0, Wq1, Wq0, Wsc, DEMB);
    build_selfT_q<<<DHID, DEMB>>>(selfw0, Sq1, Sq0, Ssc, DEMB);
    gemm_s8<<<dim3(1, nM), 512, SMEM8>>>(N_NODES, DEMB, Eq1, Eq0, Es, Sq1, Sq0, Ssc, acc, DHID);
    egemm_s8<<<EGRID, 512, SMEM8>>>(DEMB, Eq1, Eq0, Es, Wq1, Wq0, Wsc, acc);
    relu_ln_q<<<(N_NODES + 7) / 8, 256>>>(acc, ln0_g, ln0_b, xq1, xq0, xs);

    // ----- layer 1 -----
    build_wrT_q<<<NREL * DHID, DHID>>>(bases1, coeff1, Wq1, Wq0, Wsc, DHID);
    build_selfT_q<<<DHID, DHID>>>(selfw1, Sq1, Sq0, Ssc, DHID);
    gemm_s8<<<dim3(1, nM), 512, SMEM8>>>(N_NODES, DHID, xq1, xq0, xs, Sq1, Sq0, Ssc, acc, DHID);
    egemm_s8<<<EGRID, 512, SMEM8>>>(DHID, xq1, xq0, xs, Wq1, Wq0, Wsc, acc);
    relu_ln_q<<<(N_NODES + 7) / 8, 256>>>(acc, ln1_g, ln1_b, xq1, xq0, xs);

    // ----- scoring -----
    relproj_k<<<NREL, DHID>>>(relation_emb, w1, b1, rp);
    build_w1c_q<<<2 * DHID, DHID>>>(w1, w1q1, w1q0, w1sc);
    gemm_s8<<<dim3(2, nM), 512, SMEM8>>>(N_NODES, DHID, xq1, xq0, xs, w1q1, w1q0, w1sc, HPTP, 256);
    score_k<<<(NQUERY + 7) / 8, 256>>>(head_ids, relation_ids, tail_ids, HPTP, rp, w2, b2, out);
}